// round 1
// baseline (speedup 1.0000x reference)
#include <cuda_runtime.h>
#include <cuda_bf16.h>
#include <math.h>

// ---------------- problem constants ----------------
#define Bsz 8
#define Lsz 60
#define Msz (Bsz * Lsz)      // 480 rows
#define Fin 13
#define Dm  768
#define Isz 1536
#define Nst 16
#define Rlr 48
#define Kcv 4
#define NL  32
#define PROJ2 (2 * Isz)      // 3072

// ---------------- scratch (device globals, no allocation) ----------------
__device__ float g_h   [Msz * Dm];
__device__ float g_hn  [Msz * Dm];
__device__ float g_proj[Msz * PROJ2];
__device__ float g_ut  [Msz * Isz];
__device__ float g_ssm [Msz * 80];
__device__ float g_dt  [Msz * Isz];
__device__ float g_y   [Msz * Isz];
__device__ float g_f1  [Msz * 256];
__device__ float g_f2  [Msz * 256];
__device__ float g_o1  [Bsz * 256];
__device__ float g_o2  [Bsz * 256];

// ---------------- generic tiled SGEMM ----------------
// C[M,N] = act(A[M,K] @ B[K,N] + bias) ; optional accumulate / atomic (split-K)
// ACT: 0 none, 1 relu, 2 softplus
#define BM 64
#define BN 64
#define BKt 16

template<int ACT, bool BIAS, bool ACCUM, bool ATOMIC>
__global__ void gemm_k(const float* __restrict__ A, int lda,
                       const float* __restrict__ B, int ldb,
                       const float* __restrict__ bias,
                       float* __restrict__ C, int ldc,
                       int M, int N, int K)
{
    __shared__ float As[BKt][BM];
    __shared__ float Bs[BKt][BN];
    const int tid = threadIdx.x;
    const int tx = tid & 15, ty = tid >> 4;
    const int m0 = blockIdx.y * BM, n0 = blockIdx.x * BN;

    int kchunk = (K + gridDim.z - 1) / gridDim.z;
    int k_beg = blockIdx.z * kchunk;
    int k_end = min(K, k_beg + kchunk);

    float acc[4][4] = {};

    const int la_m = tid >> 2;            // 0..63
    const int la_k = (tid & 3) * 4;       // 0,4,8,12
    const int lb_k = tid >> 4;            // 0..15
    const int lb_n = (tid & 15) * 4;      // 0..60

    for (int k0 = k_beg; k0 < k_end; k0 += BKt) {
        #pragma unroll
        for (int j = 0; j < 4; j++) {
            int m = m0 + la_m, k = k0 + la_k + j;
            As[la_k + j][la_m] = (m < M && k < k_end) ? A[(size_t)m * lda + k] : 0.f;
        }
        #pragma unroll
        for (int j = 0; j < 4; j++) {
            int k = k0 + lb_k, n = n0 + lb_n + j;
            Bs[lb_k][lb_n + j] = (k < k_end && n < N) ? B[(size_t)k * ldb + n] : 0.f;
        }
        __syncthreads();
        #pragma unroll
        for (int kk = 0; kk < BKt; kk++) {
            float4 ra = *reinterpret_cast<const float4*>(&As[kk][ty * 4]);
            float4 rb = *reinterpret_cast<const float4*>(&Bs[kk][tx * 4]);
            float a4[4] = {ra.x, ra.y, ra.z, ra.w};
            float b4[4] = {rb.x, rb.y, rb.z, rb.w};
            #pragma unroll
            for (int i = 0; i < 4; i++)
                #pragma unroll
                for (int j = 0; j < 4; j++)
                    acc[i][j] = fmaf(a4[i], b4[j], acc[i][j]);
        }
        __syncthreads();
    }

    #pragma unroll
    for (int i = 0; i < 4; i++) {
        int m = m0 + ty * 4 + i;
        if (m >= M) continue;
        #pragma unroll
        for (int j = 0; j < 4; j++) {
            int n = n0 + tx * 4 + j;
            if (n >= N) continue;
            float v = acc[i][j];
            if (BIAS) v += bias[n];
            if (ACT == 1) v = fmaxf(v, 0.f);
            if (ACT == 2) v = (v > 20.f) ? v : log1pf(__expf(v));
            size_t idx = (size_t)m * ldc + n;
            if (ATOMIC)      atomicAdd(&C[idx], v);
            else if (ACCUM)  C[idx] += v;
            else             C[idx] = v;
        }
    }
}

// ---------------- RMSNorm (row of D) ----------------
__global__ void rmsnorm_k(const float* __restrict__ x, const float* __restrict__ w,
                          float* __restrict__ out, int D)
{
    int row = blockIdx.x;
    const float* xr = x + (size_t)row * D;
    float ss = 0.f;
    for (int d = threadIdx.x; d < D; d += blockDim.x) { float v = xr[d]; ss += v * v; }
    __shared__ float sm[32];
    for (int o = 16; o; o >>= 1) ss += __shfl_down_sync(0xffffffffu, ss, o);
    if ((threadIdx.x & 31) == 0) sm[threadIdx.x >> 5] = ss;
    __syncthreads();
    if (threadIdx.x < 32) {
        float v = (threadIdx.x < ((blockDim.x + 31) >> 5)) ? sm[threadIdx.x] : 0.f;
        for (int o = 16; o; o >>= 1) v += __shfl_down_sync(0xffffffffu, v, o);
        if (threadIdx.x == 0) sm[0] = v;
    }
    __syncthreads();
    float scale = rsqrtf(sm[0] / (float)D + 1e-5f);
    float* orow = out + (size_t)row * D;
    for (int d = threadIdx.x; d < D; d += blockDim.x) orow[d] = xr[d] * scale * w[d];
}

// ---------------- causal depthwise conv (K=4) + SiLU ----------------
__global__ void conv_silu_k(const float* __restrict__ proj,  // Msz x 3072, hs = cols [0,1536)
                            const float* __restrict__ cw,    // Isz x 4
                            const float* __restrict__ cb,    // Isz
                            float* __restrict__ ut)          // Msz x Isz
{
    int gid = blockIdx.x * blockDim.x + threadIdx.x;
    if (gid >= Msz * Isz) return;
    int i = gid % Isz;
    int row = gid / Isz;           // b*60 + t
    int t = row % Lsz;
    float w0 = cw[i * 4 + 0], w1 = cw[i * 4 + 1], w2 = cw[i * 4 + 2], w3 = cw[i * 4 + 3];
    float acc = cb[i];
    const float* base = proj + (size_t)row * PROJ2 + i;
    if (t >= 3) acc = fmaf(w0, base[-3 * PROJ2], acc);
    if (t >= 2) acc = fmaf(w1, base[-2 * PROJ2], acc);
    if (t >= 1) acc = fmaf(w2, base[-1 * PROJ2], acc);
    acc = fmaf(w3, base[0], acc);
    ut[gid] = acc / (1.f + __expf(-acc));   // silu
}

// ---------------- selective-scan + D skip + gate ----------------
__global__ void scan_k(const float* __restrict__ ssm,    // Msz x 80 (B at 48, C at 64)
                       const float* __restrict__ dt,     // Msz x Isz
                       const float* __restrict__ ut,     // Msz x Isz
                       const float* __restrict__ proj,   // gate at col 1536+
                       const float* __restrict__ A_log,  // Isz x 16
                       const float* __restrict__ Dp,     // Isz
                       float* __restrict__ y)            // Msz x Isz
{
    int b = blockIdx.y;
    int ci = blockIdx.x * blockDim.x + threadIdx.x;
    __shared__ float sB[Lsz][Nst], sC[Lsz][Nst];
    for (int q = threadIdx.x; q < Lsz * 32; q += blockDim.x) {
        int t = q >> 5, c = q & 31;
        float v = ssm[(size_t)(b * Lsz + t) * 80 + 48 + c];
        if (c < Nst) sB[t][c] = v; else sC[t][c - Nst] = v;
    }
    __syncthreads();

    float a[Nst];
    #pragma unroll
    for (int n = 0; n < Nst; n++) a[n] = -__expf(A_log[(size_t)ci * Nst + n]);
    float Dv = Dp[ci];
    float s[Nst];
    #pragma unroll
    for (int n = 0; n < Nst; n++) s[n] = 0.f;

    for (int t = 0; t < Lsz; t++) {
        size_t row = (size_t)b * Lsz + t;
        float dtv = dt[row * Isz + ci];
        float uv  = ut[row * Isz + ci];
        float du  = dtv * uv;
        float acc = 0.f;
        #pragma unroll
        for (int n = 0; n < Nst; n++) {
            float dA = __expf(dtv * a[n]);
            s[n] = fmaf(dA, s[n], du * sB[t][n]);
            acc = fmaf(s[n], sC[t][n], acc);
        }
        float g = proj[row * PROJ2 + Isz + ci];
        float sig = 1.f / (1.f + __expf(-g));
        y[row * Isz + ci] = (acc + uv * Dv) * (g * sig);
    }
}

// ---------------- reduction GEMM for tiny-M output head ----------------
// C[M,N] = act(A[M,K] @ B[K,N] + bias), grid = (N/32, M), block 256 (8 kgroups x 32)
__global__ void rk_gemm_k(const float* __restrict__ A, int lda,
                          const float* __restrict__ B, int ldb,
                          const float* __restrict__ bias,
                          float* __restrict__ C, int N, int K, int relu)
{
    int lane = threadIdx.x & 31;
    int kg = threadIdx.x >> 5;
    int n = blockIdx.x * 32 + lane;
    int m = blockIdx.y;
    float acc = 0.f;
    if (n < N) {
        const float* arow = A + (size_t)m * lda;
        for (int k = kg; k < K; k += 8)
            acc = fmaf(arow[k], B[(size_t)k * ldb + n], acc);
    }
    __shared__ float sm[256];
    sm[threadIdx.x] = acc;
    __syncthreads();
    if (kg == 0 && n < N) {
        float v = acc;
        #pragma unroll
        for (int g2 = 1; g2 < 8; g2++) v += sm[g2 * 32 + lane];
        v += bias[n];
        if (relu) v = fmaxf(v, 0.f);
        C[(size_t)m * N + n] = v;
    }
}

// ---------------- final dot: out[b] = o2[b,:] . w + b ----------------
__global__ void out3_k(const float* __restrict__ o2, const float* __restrict__ w,
                       const float* __restrict__ bb, float* __restrict__ out)
{
    int m = blockIdx.x;
    int tid = threadIdx.x;
    float v = o2[m * 256 + tid] * w[tid];
    for (int o = 16; o; o >>= 1) v += __shfl_down_sync(0xffffffffu, v, o);
    __shared__ float sm[8];
    if ((tid & 31) == 0) sm[tid >> 5] = v;
    __syncthreads();
    if (tid == 0) {
        float t = 0.f;
        #pragma unroll
        for (int g = 0; g < 8; g++) t += sm[g];
        out[m] = t + bb[0];
    }
}

// ---------------- host orchestration ----------------
extern "C" void kernel_launch(void* const* d_in, const int* in_sizes, int n_in,
                              void* d_out, int out_size)
{
    const float* x       = (const float*)d_in[0];
    const float* w_in1   = (const float*)d_in[1];
    const float* b_in1   = (const float*)d_in[2];
    const float* w_in2   = (const float*)d_in[3];
    const float* b_in2   = (const float*)d_in[4];
    const float* w_in3   = (const float*)d_in[5];
    const float* b_in3   = (const float*)d_in[6];
    const float* norm_w  = (const float*)d_in[7];
    const float* ipw     = (const float*)d_in[8];
    const float* cw      = (const float*)d_in[9];
    const float* cb      = (const float*)d_in[10];
    const float* xpw     = (const float*)d_in[11];
    const float* dpw     = (const float*)d_in[12];
    const float* dpb     = (const float*)d_in[13];
    const float* alog    = (const float*)d_in[14];
    const float* dprm    = (const float*)d_in[15];
    const float* opw     = (const float*)d_in[16];
    const float* norm_fw = (const float*)d_in[17];
    const float* w_o1    = (const float*)d_in[18];
    const float* b_o1    = (const float*)d_in[19];
    const float* w_o2    = (const float*)d_in[20];
    const float* b_o2    = (const float*)d_in[21];
    const float* w_o3    = (const float*)d_in[22];
    const float* b_o3    = (const float*)d_in[23];

    float *h, *hn, *proj, *ut, *ssmb, *dtb, *yb, *f1, *f2, *o1b, *o2b;
    cudaGetSymbolAddress((void**)&h,    g_h);
    cudaGetSymbolAddress((void**)&hn,   g_hn);
    cudaGetSymbolAddress((void**)&proj, g_proj);
    cudaGetSymbolAddress((void**)&ut,   g_ut);
    cudaGetSymbolAddress((void**)&ssmb, g_ssm);
    cudaGetSymbolAddress((void**)&dtb,  g_dt);
    cudaGetSymbolAddress((void**)&yb,   g_y);
    cudaGetSymbolAddress((void**)&f1,   g_f1);
    cudaGetSymbolAddress((void**)&f2,   g_f2);
    cudaGetSymbolAddress((void**)&o1b,  g_o1);
    cudaGetSymbolAddress((void**)&o2b,  g_o2);

    dim3 blk(256);

    // ---- input MLP ----
    gemm_k<1, true, false, false><<<dim3(4, 8, 1), blk>>>(
        x, Fin, w_in1, 256, b_in1, f1, 256, Msz, 256, Fin);
    gemm_k<1, true, false, false><<<dim3(4, 8, 1), blk>>>(
        f1, 256, w_in2, 256, b_in2, f2, 256, Msz, 256, 256);
    gemm_k<0, true, false, false><<<dim3(12, 8, 1), blk>>>(
        f2, 256, w_in3, Dm, b_in3, h, Dm, Msz, Dm, 256);

    // ---- 32 mamba layers ----
    for (int l = 0; l < NL; l++) {
        const float* nw_l  = norm_w + (size_t)l * Dm;
        const float* ipw_l = ipw    + (size_t)l * Dm * PROJ2;
        const float* cw_l  = cw     + (size_t)l * Isz * Kcv;
        const float* cb_l  = cb     + (size_t)l * Isz;
        const float* xpw_l = xpw    + (size_t)l * Isz * 80;
        const float* dpw_l = dpw    + (size_t)l * Rlr * Isz;
        const float* dpb_l = dpb    + (size_t)l * Isz;
        const float* al_l  = alog   + (size_t)l * Isz * Nst;
        const float* dp_l  = dprm   + (size_t)l * Isz;
        const float* opw_l = opw    + (size_t)l * Isz * Dm;

        rmsnorm_k<<<Msz, blk>>>(h, nw_l, hn, Dm);

        gemm_k<0, false, false, false><<<dim3(48, 8, 1), blk>>>(
            hn, Dm, ipw_l, PROJ2, nullptr, proj, PROJ2, Msz, PROJ2, Dm);

        conv_silu_k<<<(Msz * Isz + 255) / 256, blk>>>(proj, cw_l, cb_l, ut);

        cudaMemsetAsync(ssmb, 0, (size_t)Msz * 80 * sizeof(float));
        gemm_k<0, false, false, true><<<dim3(2, 8, 6), blk>>>(
            ut, Isz, xpw_l, 80, nullptr, ssmb, 80, Msz, 80, Isz);

        gemm_k<2, true, false, false><<<dim3(24, 8, 1), blk>>>(
            ssmb, 80, dpw_l, Isz, dpb_l, dtb, Isz, Msz, Isz, Rlr);

        scan_k<<<dim3(Isz / 256, Bsz), blk>>>(ssmb, dtb, ut, proj, al_l, dp_l, yb);

        gemm_k<0, false, true, false><<<dim3(12, 8, 1), blk>>>(
            yb, Isz, opw_l, Dm, nullptr, h, Dm, Msz, Dm, Isz);
    }

    // ---- final norm + output head ----
    rmsnorm_k<<<Msz, blk>>>(h, norm_fw, hn, Dm);
    rk_gemm_k<<<dim3(8, Bsz), blk>>>(hn, Dm * Lsz, w_o1, 256, b_o1, o1b, 256, Dm * Lsz, 1);
    rk_gemm_k<<<dim3(8, Bsz), blk>>>(o1b, 256, w_o2, 256, b_o2, o2b, 256, 256, 1);
    out3_k<<<Bsz, blk>>>(o2b, w_o3, b_o3, (float*)d_out);
}

// round 3
// speedup vs baseline: 1.0785x; 1.0785x over previous
#include <cuda_runtime.h>
#include <cuda_bf16.h>
#include <math.h>
#include <stdint.h>

// ---------------- problem constants ----------------
#define Bsz 8
#define Lsz 60
#define Msz (Bsz * Lsz)      // 480 rows
#define Fin 13
#define Dm  768
#define Isz 1536
#define Nst 16
#define Rlr 48
#define Kcv 4
#define NL  32
#define PROJ2 (2 * Isz)      // 3072

// ---------------- scratch (device globals, no allocation) ----------------
__device__ float g_h   [Msz * Dm];
__device__ float g_hn  [Msz * Dm];
__device__ float g_proj[Msz * PROJ2];
__device__ float g_ut  [Msz * Isz];
__device__ float g_ssm [Msz * 80];
__device__ float g_dt  [Msz * Isz];
__device__ float g_y   [Msz * Isz];
__device__ float g_f1  [Msz * 256];
__device__ float g_f2  [Msz * 256];
__device__ float g_o1  [Bsz * 256];
__device__ float g_o2  [Bsz * 256];

// ======================================================================
// 3xTF32 tensor-core GEMM:  C[M,N] = act(A[M,K] @ B[K,N] + bias)
// Each operand split v = hi + lo (both tf32); acc = hi*hi + hi*lo + lo*hi.
// block tile 64x64, BK=32, 128 threads (4 warps, 2x2), warp tile 32x32.
// ACT: 0 none, 1 relu, 2 softplus. ATOMIC => atomicAdd (split-K / residual).
// ======================================================================
__device__ __forceinline__ uint32_t f2tf(float f) {
    uint32_t u;
    asm("cvt.rna.tf32.f32 %0, %1;" : "=r"(u) : "f"(f));
    return u;
}

__device__ __forceinline__ void tf32_split(float v, uint32_t& hi, uint32_t& lo) {
    hi = f2tf(v);
    float r = v - __uint_as_float(hi);
    lo = f2tf(r);
}

__device__ __forceinline__ void mma_tf32(float c[4],
                                         uint32_t a0, uint32_t a1, uint32_t a2, uint32_t a3,
                                         uint32_t b0, uint32_t b1) {
    asm volatile(
        "mma.sync.aligned.m16n8k8.row.col.f32.tf32.tf32.f32 "
        "{%0,%1,%2,%3},{%4,%5,%6,%7},{%8,%9},{%0,%1,%2,%3};"
        : "+f"(c[0]), "+f"(c[1]), "+f"(c[2]), "+f"(c[3])
        : "r"(a0), "r"(a1), "r"(a2), "r"(a3), "r"(b0), "r"(b1));
}

template<int ACT, bool BIAS, bool ATOMIC>
__global__ void __launch_bounds__(128)
mma_gemm_k(const float* __restrict__ A, int lda,
           const float* __restrict__ B, int ldb,
           const float* __restrict__ bias,
           float* __restrict__ C, int ldc,
           int M, int N, int K)
{
    __shared__ uint32_t AsH[64][33];
    __shared__ uint32_t AsL[64][33];
    __shared__ uint32_t BsH[32][65];
    __shared__ uint32_t BsL[32][65];

    const int tid  = threadIdx.x;
    const int lane = tid & 31;
    const int warp = tid >> 5;
    const int warp_m = warp >> 1;       // 0..1
    const int warp_n = warp & 1;        // 0..1
    const int group = lane >> 2;        // 0..7
    const int tig   = lane & 3;         // 0..3

    const int m0 = blockIdx.y * 64;
    const int n0 = blockIdx.x * 64;

    int kchunk = (K + gridDim.z - 1) / gridDim.z;
    int k_beg  = blockIdx.z * kchunk;
    int k_end  = min(K, k_beg + kchunk);

    float acc[2][4][4];
    #pragma unroll
    for (int i = 0; i < 2; i++)
        #pragma unroll
        for (int j = 0; j < 4; j++)
            #pragma unroll
            for (int q = 0; q < 4; q++)
                acc[i][j][q] = 0.f;

    for (int k0 = k_beg; k0 < k_end; k0 += 32) {
        const int kw = k_end - k0;
        // stage A: 64x32
        #pragma unroll
        for (int it = 0; it < 16; ++it) {
            int idx = tid + it * 128;
            int m = idx >> 5, k = idx & 31;
            float v = 0.f;
            if (m0 + m < M && k < kw) v = __ldg(&A[(size_t)(m0 + m) * lda + k0 + k]);
            uint32_t hi, lo; tf32_split(v, hi, lo);
            AsH[m][k] = hi; AsL[m][k] = lo;
        }
        // stage B: 32x64
        #pragma unroll
        for (int it = 0; it < 16; ++it) {
            int idx = tid + it * 128;
            int k = idx >> 6, n = idx & 63;
            float v = 0.f;
            if (k < kw && n0 + n < N) v = __ldg(&B[(size_t)(k0 + k) * ldb + n0 + n]);
            uint32_t hi, lo; tf32_split(v, hi, lo);
            BsH[k][n] = hi; BsL[k][n] = lo;
        }
        __syncthreads();

        #pragma unroll
        for (int ks = 0; ks < 4; ks++) {
            const int kk = ks * 8;
            uint32_t afH[2][4], afL[2][4];
            #pragma unroll
            for (int i = 0; i < 2; i++) {
                int r = warp_m * 32 + i * 16 + group;
                afH[i][0] = AsH[r    ][kk + tig];
                afH[i][1] = AsH[r + 8][kk + tig];
                afH[i][2] = AsH[r    ][kk + tig + 4];
                afH[i][3] = AsH[r + 8][kk + tig + 4];
                afL[i][0] = AsL[r    ][kk + tig];
                afL[i][1] = AsL[r + 8][kk + tig];
                afL[i][2] = AsL[r    ][kk + tig + 4];
                afL[i][3] = AsL[r + 8][kk + tig + 4];
            }
            uint32_t bfH[4][2], bfL[4][2];
            #pragma unroll
            for (int j = 0; j < 4; j++) {
                int c = warp_n * 32 + j * 8 + group;
                bfH[j][0] = BsH[kk + tig    ][c];
                bfH[j][1] = BsH[kk + tig + 4][c];
                bfL[j][0] = BsL[kk + tig    ][c];
                bfL[j][1] = BsL[kk + tig + 4][c];
            }
            #pragma unroll
            for (int i = 0; i < 2; i++)
                #pragma unroll
                for (int j = 0; j < 4; j++) {
                    // lo terms first (smaller magnitude), hi*hi last
                    mma_tf32(acc[i][j], afL[i][0], afL[i][1], afL[i][2], afL[i][3],
                             bfH[j][0], bfH[j][1]);
                    mma_tf32(acc[i][j], afH[i][0], afH[i][1], afH[i][2], afH[i][3],
                             bfL[j][0], bfL[j][1]);
                    mma_tf32(acc[i][j], afH[i][0], afH[i][1], afH[i][2], afH[i][3],
                             bfH[j][0], bfH[j][1]);
                }
        }
        __syncthreads();
    }

    // epilogue
    #pragma unroll
    for (int i = 0; i < 2; i++) {
        #pragma unroll
        for (int j = 0; j < 4; j++) {
            int row = m0 + warp_m * 32 + i * 16 + group;
            int col = n0 + warp_n * 32 + j * 8 + tig * 2;
            #pragma unroll
            for (int q = 0; q < 4; q++) {
                int r = row + (q >> 1) * 8;
                int c = col + (q & 1);
                if (r >= M || c >= N) continue;
                float v = acc[i][j][q];
                if (BIAS) v += bias[c];
                if (ACT == 1) v = fmaxf(v, 0.f);
                if (ACT == 2) v = (v > 20.f) ? v : log1pf(__expf(v));
                size_t idx = (size_t)r * ldc + c;
                if (ATOMIC) atomicAdd(&C[idx], v);
                else        C[idx] = v;
            }
        }
    }
}

// ---------------- fp32 fallback GEMM (input MLP, runs once) ----------------
#define BM 64
#define BN 64
#define BKt 16

template<int ACT, bool BIAS>
__global__ void gemm_k(const float* __restrict__ A, int lda,
                       const float* __restrict__ B, int ldb,
                       const float* __restrict__ bias,
                       float* __restrict__ C, int ldc,
                       int M, int N, int K)
{
    __shared__ float As[BKt][BM];
    __shared__ float Bs[BKt][BN];
    const int tid = threadIdx.x;
    const int tx = tid & 15, ty = tid >> 4;
    const int m0 = blockIdx.y * BM, n0 = blockIdx.x * BN;

    float acc[4][4] = {};
    const int la_m = tid >> 2;
    const int la_k = (tid & 3) * 4;
    const int lb_k = tid >> 4;
    const int lb_n = (tid & 15) * 4;

    for (int k0 = 0; k0 < K; k0 += BKt) {
        #pragma unroll
        for (int j = 0; j < 4; j++) {
            int m = m0 + la_m, k = k0 + la_k + j;
            As[la_k + j][la_m] = (m < M && k < K) ? A[(size_t)m * lda + k] : 0.f;
        }
        #pragma unroll
        for (int j = 0; j < 4; j++) {
            int k = k0 + lb_k, n = n0 + lb_n + j;
            Bs[lb_k][lb_n + j] = (k < K && n < N) ? B[(size_t)k * ldb + n] : 0.f;
        }
        __syncthreads();
        #pragma unroll
        for (int kk = 0; kk < BKt; kk++) {
            float4 ra = *reinterpret_cast<const float4*>(&As[kk][ty * 4]);
            float4 rb = *reinterpret_cast<const float4*>(&Bs[kk][tx * 4]);
            float a4[4] = {ra.x, ra.y, ra.z, ra.w};
            float b4[4] = {rb.x, rb.y, rb.z, rb.w};
            #pragma unroll
            for (int i = 0; i < 4; i++)
                #pragma unroll
                for (int j = 0; j < 4; j++)
                    acc[i][j] = fmaf(a4[i], b4[j], acc[i][j]);
        }
        __syncthreads();
    }

    #pragma unroll
    for (int i = 0; i < 4; i++) {
        int m = m0 + ty * 4 + i;
        if (m >= M) continue;
        #pragma unroll
        for (int j = 0; j < 4; j++) {
            int n = n0 + tx * 4 + j;
            if (n >= N) continue;
            float v = acc[i][j];
            if (BIAS) v += bias[n];
            if (ACT == 1) v = fmaxf(v, 0.f);
            C[(size_t)m * ldc + n] = v;
        }
    }
}

// ---------------- RMSNorm ----------------
__global__ void rmsnorm_k(const float* __restrict__ x, const float* __restrict__ w,
                          float* __restrict__ out, int D)
{
    int row = blockIdx.x;
    const float* xr = x + (size_t)row * D;
    float ss = 0.f;
    for (int d = threadIdx.x; d < D; d += blockDim.x) { float v = xr[d]; ss += v * v; }
    __shared__ float sm[32];
    for (int o = 16; o; o >>= 1) ss += __shfl_down_sync(0xffffffffu, ss, o);
    if ((threadIdx.x & 31) == 0) sm[threadIdx.x >> 5] = ss;
    __syncthreads();
    if (threadIdx.x < 32) {
        float v = (threadIdx.x < ((blockDim.x + 31) >> 5)) ? sm[threadIdx.x] : 0.f;
        for (int o = 16; o; o >>= 1) v += __shfl_down_sync(0xffffffffu, v, o);
        if (threadIdx.x == 0) sm[0] = v;
    }
    __syncthreads();
    float scale = rsqrtf(sm[0] / (float)D + 1e-5f);
    float* orow = out + (size_t)row * D;
    for (int d = threadIdx.x; d < D; d += blockDim.x) orow[d] = xr[d] * scale * w[d];
}

// ---------------- causal depthwise conv (K=4) + SiLU ----------------
__global__ void conv_silu_k(const float* __restrict__ proj,
                            const float* __restrict__ cw,
                            const float* __restrict__ cb,
                            float* __restrict__ ut)
{
    int gid = blockIdx.x * blockDim.x + threadIdx.x;
    if (gid >= Msz * Isz) return;
    int i = gid % Isz;
    int row = gid / Isz;
    int t = row % Lsz;
    float w0 = cw[i * 4 + 0], w1 = cw[i * 4 + 1], w2 = cw[i * 4 + 2], w3 = cw[i * 4 + 3];
    float acc = cb[i];
    const float* base = proj + (size_t)row * PROJ2 + i;
    if (t >= 3) acc = fmaf(w0, base[-3 * PROJ2], acc);
    if (t >= 2) acc = fmaf(w1, base[-2 * PROJ2], acc);
    if (t >= 1) acc = fmaf(w2, base[-1 * PROJ2], acc);
    acc = fmaf(w3, base[0], acc);
    ut[gid] = acc / (1.f + __expf(-acc));
}

// ---------------- selective-scan + D skip + gate ----------------
__global__ void __launch_bounds__(128)
scan_k(const float* __restrict__ ssm,
       const float* __restrict__ dt,
       const float* __restrict__ ut,
       const float* __restrict__ proj,
       const float* __restrict__ A_log,
       const float* __restrict__ Dp,
       float* __restrict__ y)
{
    int b = blockIdx.y;
    int ci = blockIdx.x * blockDim.x + threadIdx.x;
    __shared__ float sB[Lsz][Nst], sC[Lsz][Nst];
    for (int q = threadIdx.x; q < Lsz * 32; q += blockDim.x) {
        int t = q >> 5, c = q & 31;
        float v = ssm[(size_t)(b * Lsz + t) * 80 + 48 + c];
        if (c < Nst) sB[t][c] = v; else sC[t][c - Nst] = v;
    }
    __syncthreads();

    float a[Nst];
    #pragma unroll
    for (int n = 0; n < Nst; n++) a[n] = -__expf(A_log[(size_t)ci * Nst + n]);
    float Dv = Dp[ci];
    float s[Nst];
    #pragma unroll
    for (int n = 0; n < Nst; n++) s[n] = 0.f;

    for (int t = 0; t < Lsz; t++) {
        size_t row = (size_t)b * Lsz + t;
        float dtv = dt[row * Isz + ci];
        float uv  = ut[row * Isz + ci];
        float du  = dtv * uv;
        float acc = 0.f;
        #pragma unroll
        for (int n = 0; n < Nst; n++) {
            float dA = __expf(dtv * a[n]);
            s[n] = fmaf(dA, s[n], du * sB[t][n]);
            acc = fmaf(s[n], sC[t][n], acc);
        }
        float g = proj[row * PROJ2 + Isz + ci];
        float sig = 1.f / (1.f + __expf(-g));
        y[row * Isz + ci] = (acc + uv * Dv) * (g * sig);
    }
}

// ---------------- reduction GEMM for tiny-M output head ----------------
__global__ void rk_gemm_k(const float* __restrict__ A, int lda,
                          const float* __restrict__ B, int ldb,
                          const float* __restrict__ bias,
                          float* __restrict__ C, int N, int K, int relu)
{
    int lane = threadIdx.x & 31;
    int kg = threadIdx.x >> 5;
    int n = blockIdx.x * 32 + lane;
    int m = blockIdx.y;
    float acc = 0.f;
    if (n < N) {
        const float* arow = A + (size_t)m * lda;
        for (int k = kg; k < K; k += 8)
            acc = fmaf(arow[k], B[(size_t)k * ldb + n], acc);
    }
    __shared__ float sm[256];
    sm[threadIdx.x] = acc;
    __syncthreads();
    if (kg == 0 && n < N) {
        float v = acc;
        #pragma unroll
        for (int g2 = 1; g2 < 8; g2++) v += sm[g2 * 32 + lane];
        v += bias[n];
        if (relu) v = fmaxf(v, 0.f);
        C[(size_t)m * N + n] = v;
    }
}

// ---------------- final dot ----------------
__global__ void out3_k(const float* __restrict__ o2, const float* __restrict__ w,
                       const float* __restrict__ bb, float* __restrict__ out)
{
    int m = blockIdx.x;
    int tid = threadIdx.x;
    float v = o2[m * 256 + tid] * w[tid];
    for (int o = 16; o; o >>= 1) v += __shfl_down_sync(0xffffffffu, v, o);
    __shared__ float sm[8];
    if ((tid & 31) == 0) sm[tid >> 5] = v;
    __syncthreads();
    if (tid == 0) {
        float t = 0.f;
        #pragma unroll
        for (int g = 0; g < 8; g++) t += sm[g];
        out[m] = t + bb[0];
    }
}

// ---------------- host orchestration ----------------
extern "C" void kernel_launch(void* const* d_in, const int* in_sizes, int n_in,
                              void* d_out, int out_size)
{
    const float* x       = (const float*)d_in[0];
    const float* w_in1   = (const float*)d_in[1];
    const float* b_in1   = (const float*)d_in[2];
    const float* w_in2   = (const float*)d_in[3];
    const float* b_in2   = (const float*)d_in[4];
    const float* w_in3   = (const float*)d_in[5];
    const float* b_in3   = (const float*)d_in[6];
    const float* norm_w  = (const float*)d_in[7];
    const float* ipw     = (const float*)d_in[8];
    const float* cw      = (const float*)d_in[9];
    const float* cb      = (const float*)d_in[10];
    const float* xpw     = (const float*)d_in[11];
    const float* dpw     = (const float*)d_in[12];
    const float* dpb     = (const float*)d_in[13];
    const float* alog    = (const float*)d_in[14];
    const float* dprm    = (const float*)d_in[15];
    const float* opw     = (const float*)d_in[16];
    const float* norm_fw = (const float*)d_in[17];
    const float* w_o1    = (const float*)d_in[18];
    const float* b_o1    = (const float*)d_in[19];
    const float* w_o2    = (const float*)d_in[20];
    const float* b_o2    = (const float*)d_in[21];
    const float* w_o3    = (const float*)d_in[22];
    const float* b_o3    = (const float*)d_in[23];

    float *h, *hn, *proj, *ut, *ssmb, *dtb, *yb, *f1, *f2, *o1b, *o2b;
    cudaGetSymbolAddress((void**)&h,    g_h);
    cudaGetSymbolAddress((void**)&hn,   g_hn);
    cudaGetSymbolAddress((void**)&proj, g_proj);
    cudaGetSymbolAddress((void**)&ut,   g_ut);
    cudaGetSymbolAddress((void**)&ssmb, g_ssm);
    cudaGetSymbolAddress((void**)&dtb,  g_dt);
    cudaGetSymbolAddress((void**)&yb,   g_y);
    cudaGetSymbolAddress((void**)&f1,   g_f1);
    cudaGetSymbolAddress((void**)&f2,   g_f2);
    cudaGetSymbolAddress((void**)&o1b,  g_o1);
    cudaGetSymbolAddress((void**)&o2b,  g_o2);

    dim3 blk256(256), blk128(128);

    // ---- input MLP (fp32, runs once) ----
    gemm_k<1, true><<<dim3(4, 8, 1), blk256>>>(
        x, Fin, w_in1, 256, b_in1, f1, 256, Msz, 256, Fin);
    gemm_k<1, true><<<dim3(4, 8, 1), blk256>>>(
        f1, 256, w_in2, 256, b_in2, f2, 256, Msz, 256, 256);
    gemm_k<0, true><<<dim3(12, 8, 1), blk256>>>(
        f2, 256, w_in3, Dm, b_in3, h, Dm, Msz, Dm, 256);

    // ---- 32 mamba layers ----
    for (int l = 0; l < NL; l++) {
        const float* nw_l  = norm_w + (size_t)l * Dm;
        const float* ipw_l = ipw    + (size_t)l * Dm * PROJ2;
        const float* cw_l  = cw     + (size_t)l * Isz * Kcv;
        const float* cb_l  = cb     + (size_t)l * Isz;
        const float* xpw_l = xpw    + (size_t)l * Isz * 80;
        const float* dpw_l = dpw    + (size_t)l * Rlr * Isz;
        const float* dpb_l = dpb    + (size_t)l * Isz;
        const float* al_l  = alog   + (size_t)l * Isz * Nst;
        const float* dp_l  = dprm   + (size_t)l * Isz;
        const float* opw_l = opw    + (size_t)l * Isz * Dm;

        rmsnorm_k<<<Msz, blk256>>>(h, nw_l, hn, Dm);

        // in_proj: [480,768] x [768,3072]
        mma_gemm_k<0, false, false><<<dim3(48, 8, 1), blk128>>>(
            hn, Dm, ipw_l, PROJ2, nullptr, proj, PROJ2, Msz, PROJ2, Dm);

        conv_silu_k<<<(Msz * Isz + 255) / 256, blk256>>>(proj, cw_l, cb_l, ut);

        // x_proj: [480,1536] x [1536,80], split-K=8 with atomics
        cudaMemsetAsync(ssmb, 0, (size_t)Msz * 80 * sizeof(float));
        mma_gemm_k<0, false, true><<<dim3(2, 8, 8), blk128>>>(
            ut, Isz, xpw_l, 80, nullptr, ssmb, 80, Msz, 80, Isz);

        // dt_proj: [480,48] x [48,1536], softplus + bias
        mma_gemm_k<2, true, false><<<dim3(24, 8, 1), blk128>>>(
            ssmb, 80, dpw_l, Isz, dpb_l, dtb, Isz, Msz, Isz, Rlr);

        scan_k<<<dim3(Isz / 128, Bsz), blk128>>>(ssmb, dtb, ut, proj, al_l, dp_l, yb);

        // out_proj: [480,1536] x [1536,768], split-K=2, atomic residual add into h
        mma_gemm_k<0, false, true><<<dim3(12, 8, 2), blk128>>>(
            yb, Isz, opw_l, Dm, nullptr, h, Dm, Msz, Dm, Isz);
    }

    // ---- final norm + output head ----
    rmsnorm_k<<<Msz, blk256>>>(h, norm_fw, hn, Dm);
    rk_gemm_k<<<dim3(8, Bsz), blk256>>>(hn, Dm * Lsz, w_o1, 256, b_o1, o1b, 256, Dm * Lsz, 1);
    rk_gemm_k<<<dim3(8, Bsz), blk256>>>(o1b, 256, w_o2, 256, b_o2, o2b, 256, 256, 1);
    out3_k<<<Bsz, blk256>>>(o2b, w_o3, b_o3, (float*)d_out);
}

// round 4
// speedup vs baseline: 1.1498x; 1.0661x over previous
#include <cuda_runtime.h>
#include <cuda_bf16.h>
#include <math.h>
#include <stdint.h>

// ---------------- problem constants ----------------
#define Bsz 8
#define Lsz 60
#define Msz (Bsz * Lsz)      // 480 rows
#define Fin 13
#define Dm  768
#define Isz 1536
#define Nst 16
#define Rlr 48
#define Kcv 4
#define NL  32
#define PROJ2 (2 * Isz)      // 3072

// ---------------- scratch (device globals, no allocation) ----------------
__device__ float g_h   [Msz * Dm];
__device__ float g_hn  [Msz * Dm];
__device__ float g_proj[Msz * PROJ2];
__device__ float g_ut  [Msz * Isz];
__device__ float g_ssm [Msz * 80];
__device__ float g_dt  [Msz * Isz];
__device__ float g_y   [Msz * Isz];
__device__ float g_f1  [Msz * 256];
__device__ float g_f2  [Msz * 256];
__device__ float g_o1  [Bsz * 256];
__device__ float g_o2  [Bsz * 256];

// ======================================================================
// 3xTF32 tensor-core GEMM with fragment-permuted smem staging.
// C[M,N] = act(A[M,K] @ B[K,N] + bias)
// block tile 64x64, BK=32, 128 threads (4 warps 2x2), warp tile 32x32.
// Staging scatters tf32 hi/lo values directly into mma-fragment order so
// the inner loop uses ld.shared.v4 (1 LDS per A-fragment, 2 per B ks-step).
// ACT: 0 none, 1 relu, 2 softplus. ATOMIC => atomicAdd (split-K/residual).
// ======================================================================
__device__ __forceinline__ uint32_t f2tf(float f) {
    uint32_t u;
    asm("cvt.rna.tf32.f32 %0, %1;" : "=r"(u) : "f"(f));
    return u;
}

__device__ __forceinline__ void tf32_split(float v, uint32_t& hi, uint32_t& lo) {
    hi = f2tf(v);
    float r = v - __uint_as_float(hi);
    lo = f2tf(r);
}

__device__ __forceinline__ void mma_tf32(float c[4],
                                         uint32_t a0, uint32_t a1, uint32_t a2, uint32_t a3,
                                         uint32_t b0, uint32_t b1) {
    asm volatile(
        "mma.sync.aligned.m16n8k8.row.col.f32.tf32.tf32.f32 "
        "{%0,%1,%2,%3},{%4,%5,%6,%7},{%8,%9},{%0,%1,%2,%3};"
        : "+f"(c[0]), "+f"(c[1]), "+f"(c[2]), "+f"(c[3])
        : "r"(a0), "r"(a1), "r"(a2), "r"(a3), "r"(b0), "r"(b1));
}

template<int ACT, bool BIAS, bool ATOMIC>
__global__ void __launch_bounds__(128)
mma_gemm_k(const float* __restrict__ A, int lda,
           const float* __restrict__ B, int ldb,
           const float* __restrict__ bias,
           float* __restrict__ C, int ldc,
           int M, int N, int K)
{
    // A fragments: [wm(2)][i(2)][ks(4)][lane(32)] uint4
    // B fragments: [wn(2)][ks(4)][pair(2)][lane(32)] uint4
    __shared__ uint4 AsPH[512];
    __shared__ uint4 AsPL[512];
    __shared__ uint4 BsPH[512];
    __shared__ uint4 BsPL[512];

    const int tid  = threadIdx.x;
    const int lane = tid & 31;
    const int warp = tid >> 5;
    const int warp_m = warp >> 1;
    const int warp_n = warp & 1;
    const int group = lane >> 2;
    const int tig   = lane & 3;

    const int m0 = blockIdx.y * 64;
    const int n0 = blockIdx.x * 64;

    int kchunk = (K + gridDim.z - 1) / gridDim.z;
    int k_beg  = blockIdx.z * kchunk;
    int k_end  = min(K, k_beg + kchunk);

    uint32_t* wAH = (uint32_t*)AsPH;
    uint32_t* wAL = (uint32_t*)AsPL;
    uint32_t* wBH = (uint32_t*)BsPH;
    uint32_t* wBL = (uint32_t*)BsPL;

    float acc[2][4][4];
    #pragma unroll
    for (int i = 0; i < 2; i++)
        #pragma unroll
        for (int j = 0; j < 4; j++)
            #pragma unroll
            for (int q = 0; q < 4; q++)
                acc[i][j][q] = 0.f;

    for (int k0 = k_beg; k0 < k_end; k0 += 32) {
        const int kw = k_end - k0;
        // ---- stage A: 64x32, scatter into fragment order ----
        #pragma unroll
        for (int it = 0; it < 16; ++it) {
            int idx = tid + it * 128;
            int m = idx >> 5, k = idx & 31;
            float v = 0.f;
            if (m0 + m < M && k < kw) v = __ldg(&A[(size_t)(m0 + m) * lda + k0 + k]);
            uint32_t hi, lo; tf32_split(v, hi, lo);
            int slot = ((((m >> 5) * 2 + ((m >> 4) & 1)) * 4 + (k >> 3)) * 32
                        + (m & 7) * 4 + (k & 3)) * 4
                       + ((m >> 3) & 1) + ((k >> 2) & 1) * 2;
            wAH[slot] = hi; wAL[slot] = lo;
        }
        // ---- stage B: 32x64, scatter into fragment order ----
        #pragma unroll
        for (int it = 0; it < 16; ++it) {
            int idx = tid + it * 128;
            int k = idx >> 6, n = idx & 63;
            float v = 0.f;
            if (k < kw && n0 + n < N) v = __ldg(&B[(size_t)(k0 + k) * ldb + n0 + n]);
            uint32_t hi, lo; tf32_split(v, hi, lo);
            int slot = ((((n >> 5) * 4 + (k >> 3)) * 2 + ((n >> 4) & 1)) * 32
                        + (n & 7) * 4 + (k & 3)) * 4
                       + ((n >> 3) & 1) * 2 + ((k >> 2) & 1);
            wBH[slot] = hi; wBL[slot] = lo;
        }
        __syncthreads();

        #pragma unroll
        for (int ks = 0; ks < 4; ks++) {
            uint4 aH[2], aL[2];
            #pragma unroll
            for (int i = 0; i < 2; i++) {
                int base = ((warp_m * 2 + i) * 4 + ks) * 32 + lane;
                aH[i] = AsPH[base];
                aL[i] = AsPL[base];
            }
            uint4 bH[2], bL[2];
            #pragma unroll
            for (int p = 0; p < 2; p++) {
                int base = ((warp_n * 4 + ks) * 2 + p) * 32 + lane;
                bH[p] = BsPH[base];
                bL[p] = BsPL[base];
            }
            #pragma unroll
            for (int i = 0; i < 2; i++) {
                #pragma unroll
                for (int j = 0; j < 4; j++) {
                    int p = j >> 1;
                    uint32_t b0H = (j & 1) ? ((p ? bH[1].z : bH[0].z)) : ((p ? bH[1].x : bH[0].x));
                    uint32_t b1H = (j & 1) ? ((p ? bH[1].w : bH[0].w)) : ((p ? bH[1].y : bH[0].y));
                    uint32_t b0L = (j & 1) ? ((p ? bL[1].z : bL[0].z)) : ((p ? bL[1].x : bL[0].x));
                    uint32_t b1L = (j & 1) ? ((p ? bL[1].w : bL[0].w)) : ((p ? bL[1].y : bL[0].y));
                    // lo terms first, hi*hi last
                    mma_tf32(acc[i][j], aL[i].x, aL[i].y, aL[i].z, aL[i].w, b0H, b1H);
                    mma_tf32(acc[i][j], aH[i].x, aH[i].y, aH[i].z, aH[i].w, b0L, b1L);
                    mma_tf32(acc[i][j], aH[i].x, aH[i].y, aH[i].z, aH[i].w, b0H, b1H);
                }
            }
        }
        __syncthreads();
    }

    // epilogue
    #pragma unroll
    for (int i = 0; i < 2; i++) {
        #pragma unroll
        for (int j = 0; j < 4; j++) {
            int row = m0 + warp_m * 32 + i * 16 + group;
            int col = n0 + warp_n * 32 + j * 8 + tig * 2;
            #pragma unroll
            for (int q = 0; q < 4; q++) {
                int r = row + (q >> 1) * 8;
                int c = col + (q & 1);
                if (r >= M || c >= N) continue;
                float v = acc[i][j][q];
                if (BIAS) v += bias[c];
                if (ACT == 1) v = fmaxf(v, 0.f);
                if (ACT == 2) v = (v > 20.f) ? v : log1pf(__expf(v));
                size_t idx = (size_t)r * ldc + c;
                if (ATOMIC) atomicAdd(&C[idx], v);
                else        C[idx] = v;
            }
        }
    }
}

// ---------------- fp32 fallback GEMM (input MLP, runs once) ----------------
#define BM 64
#define BN 64
#define BKt 16

template<int ACT, bool BIAS>
__global__ void gemm_k(const float* __restrict__ A, int lda,
                       const float* __restrict__ B, int ldb,
                       const float* __restrict__ bias,
                       float* __restrict__ C, int ldc,
                       int M, int N, int K)
{
    __shared__ float As[BKt][BM];
    __shared__ float Bs[BKt][BN];
    const int tid = threadIdx.x;
    const int tx = tid & 15, ty = tid >> 4;
    const int m0 = blockIdx.y * BM, n0 = blockIdx.x * BN;

    float acc[4][4] = {};
    const int la_m = tid >> 2;
    const int la_k = (tid & 3) * 4;
    const int lb_k = tid >> 4;
    const int lb_n = (tid & 15) * 4;

    for (int k0 = 0; k0 < K; k0 += BKt) {
        #pragma unroll
        for (int j = 0; j < 4; j++) {
            int m = m0 + la_m, k = k0 + la_k + j;
            As[la_k + j][la_m] = (m < M && k < K) ? A[(size_t)m * lda + k] : 0.f;
        }
        #pragma unroll
        for (int j = 0; j < 4; j++) {
            int k = k0 + lb_k, n = n0 + lb_n + j;
            Bs[lb_k][lb_n + j] = (k < K && n < N) ? B[(size_t)k * ldb + n] : 0.f;
        }
        __syncthreads();
        #pragma unroll
        for (int kk = 0; kk < BKt; kk++) {
            float4 ra = *reinterpret_cast<const float4*>(&As[kk][ty * 4]);
            float4 rb = *reinterpret_cast<const float4*>(&Bs[kk][tx * 4]);
            float a4[4] = {ra.x, ra.y, ra.z, ra.w};
            float b4[4] = {rb.x, rb.y, rb.z, rb.w};
            #pragma unroll
            for (int i = 0; i < 4; i++)
                #pragma unroll
                for (int j = 0; j < 4; j++)
                    acc[i][j] = fmaf(a4[i], b4[j], acc[i][j]);
        }
        __syncthreads();
    }

    #pragma unroll
    for (int i = 0; i < 4; i++) {
        int m = m0 + ty * 4 + i;
        if (m >= M) continue;
        #pragma unroll
        for (int j = 0; j < 4; j++) {
            int n = n0 + tx * 4 + j;
            if (n >= N) continue;
            float v = acc[i][j];
            if (BIAS) v += bias[n];
            if (ACT == 1) v = fmaxf(v, 0.f);
            C[(size_t)m * ldc + n] = v;
        }
    }
}

// ---------------- RMSNorm ----------------
__global__ void rmsnorm_k(const float* __restrict__ x, const float* __restrict__ w,
                          float* __restrict__ out, int D)
{
    int row = blockIdx.x;
    const float* xr = x + (size_t)row * D;
    float ss = 0.f;
    for (int d = threadIdx.x; d < D; d += blockDim.x) { float v = xr[d]; ss += v * v; }
    __shared__ float sm[32];
    for (int o = 16; o; o >>= 1) ss += __shfl_down_sync(0xffffffffu, ss, o);
    if ((threadIdx.x & 31) == 0) sm[threadIdx.x >> 5] = ss;
    __syncthreads();
    if (threadIdx.x < 32) {
        float v = (threadIdx.x < ((blockDim.x + 31) >> 5)) ? sm[threadIdx.x] : 0.f;
        for (int o = 16; o; o >>= 1) v += __shfl_down_sync(0xffffffffu, v, o);
        if (threadIdx.x == 0) sm[0] = v;
    }
    __syncthreads();
    float scale = rsqrtf(sm[0] / (float)D + 1e-5f);
    float* orow = out + (size_t)row * D;
    for (int d = threadIdx.x; d < D; d += blockDim.x) orow[d] = xr[d] * scale * w[d];
}

// ---------------- causal depthwise conv (K=4) + SiLU ----------------
__global__ void conv_silu_k(const float* __restrict__ proj,
                            const float* __restrict__ cw,
                            const float* __restrict__ cb,
                            float* __restrict__ ut)
{
    int gid = blockIdx.x * blockDim.x + threadIdx.x;
    if (gid >= Msz * Isz) return;
    int i = gid % Isz;
    int row = gid / Isz;
    int t = row % Lsz;
    float w0 = cw[i * 4 + 0], w1 = cw[i * 4 + 1], w2 = cw[i * 4 + 2], w3 = cw[i * 4 + 3];
    float acc = cb[i];
    const float* base = proj + (size_t)row * PROJ2 + i;
    if (t >= 3) acc = fmaf(w0, base[-3 * PROJ2], acc);
    if (t >= 2) acc = fmaf(w1, base[-2 * PROJ2], acc);
    if (t >= 1) acc = fmaf(w2, base[-1 * PROJ2], acc);
    acc = fmaf(w3, base[0], acc);
    ut[gid] = acc / (1.f + __expf(-acc));
}

// ---------------- selective-scan + D skip + gate ----------------
__global__ void __launch_bounds__(128)
scan_k(const float* __restrict__ ssm,
       const float* __restrict__ dt,
       const float* __restrict__ ut,
       const float* __restrict__ proj,
       const float* __restrict__ A_log,
       const float* __restrict__ Dp,
       float* __restrict__ y)
{
    int b = blockIdx.y;
    int ci = blockIdx.x * blockDim.x + threadIdx.x;
    __shared__ float sB[Lsz][Nst], sC[Lsz][Nst];
    for (int q = threadIdx.x; q < Lsz * 32; q += blockDim.x) {
        int t = q >> 5, c = q & 31;
        float v = ssm[(size_t)(b * Lsz + t) * 80 + 48 + c];
        if (c < Nst) sB[t][c] = v; else sC[t][c - Nst] = v;
    }
    __syncthreads();

    float a[Nst];
    #pragma unroll
    for (int n = 0; n < Nst; n++) a[n] = -__expf(A_log[(size_t)ci * Nst + n]);
    float Dv = Dp[ci];
    float s[Nst];
    #pragma unroll
    for (int n = 0; n < Nst; n++) s[n] = 0.f;

    for (int t = 0; t < Lsz; t++) {
        size_t row = (size_t)b * Lsz + t;
        float dtv = dt[row * Isz + ci];
        float uv  = ut[row * Isz + ci];
        float du  = dtv * uv;
        float acc = 0.f;
        #pragma unroll
        for (int n = 0; n < Nst; n++) {
            float dA = __expf(dtv * a[n]);
            s[n] = fmaf(dA, s[n], du * sB[t][n]);
            acc = fmaf(s[n], sC[t][n], acc);
        }
        float g = proj[row * PROJ2 + Isz + ci];
        float sig = 1.f / (1.f + __expf(-g));
        y[row * Isz + ci] = (acc + uv * Dv) * (g * sig);
    }
}

// ---------------- reduction GEMM for tiny-M output head ----------------
__global__ void rk_gemm_k(const float* __restrict__ A, int lda,
                          const float* __restrict__ B, int ldb,
                          const float* __restrict__ bias,
                          float* __restrict__ C, int N, int K, int relu)
{
    int lane = threadIdx.x & 31;
    int kg = threadIdx.x >> 5;
    int n = blockIdx.x * 32 + lane;
    int m = blockIdx.y;
    float acc = 0.f;
    if (n < N) {
        const float* arow = A + (size_t)m * lda;
        for (int k = kg; k < K; k += 8)
            acc = fmaf(arow[k], B[(size_t)k * ldb + n], acc);
    }
    __shared__ float sm[256];
    sm[threadIdx.x] = acc;
    __syncthreads();
    if (kg == 0 && n < N) {
        float v = acc;
        #pragma unroll
        for (int g2 = 1; g2 < 8; g2++) v += sm[g2 * 32 + lane];
        v += bias[n];
        if (relu) v = fmaxf(v, 0.f);
        C[(size_t)m * N + n] = v;
    }
}

// ---------------- final dot ----------------
__global__ void out3_k(const float* __restrict__ o2, const float* __restrict__ w,
                       const float* __restrict__ bb, float* __restrict__ out)
{
    int m = blockIdx.x;
    int tid = threadIdx.x;
    float v = o2[m * 256 + tid] * w[tid];
    for (int o = 16; o; o >>= 1) v += __shfl_down_sync(0xffffffffu, v, o);
    __shared__ float sm[8];
    if ((tid & 31) == 0) sm[tid >> 5] = v;
    __syncthreads();
    if (tid == 0) {
        float t = 0.f;
        #pragma unroll
        for (int g = 0; g < 8; g++) t += sm[g];
        out[m] = t + bb[0];
    }
}

// ---------------- host orchestration ----------------
extern "C" void kernel_launch(void* const* d_in, const int* in_sizes, int n_in,
                              void* d_out, int out_size)
{
    const float* x       = (const float*)d_in[0];
    const float* w_in1   = (const float*)d_in[1];
    const float* b_in1   = (const float*)d_in[2];
    const float* w_in2   = (const float*)d_in[3];
    const float* b_in2   = (const float*)d_in[4];
    const float* w_in3   = (const float*)d_in[5];
    const float* b_in3   = (const float*)d_in[6];
    const float* norm_w  = (const float*)d_in[7];
    const float* ipw     = (const float*)d_in[8];
    const float* cw      = (const float*)d_in[9];
    const float* cb      = (const float*)d_in[10];
    const float* xpw     = (const float*)d_in[11];
    const float* dpw     = (const float*)d_in[12];
    const float* dpb     = (const float*)d_in[13];
    const float* alog    = (const float*)d_in[14];
    const float* dprm    = (const float*)d_in[15];
    const float* opw     = (const float*)d_in[16];
    const float* norm_fw = (const float*)d_in[17];
    const float* w_o1    = (const float*)d_in[18];
    const float* b_o1    = (const float*)d_in[19];
    const float* w_o2    = (const float*)d_in[20];
    const float* b_o2    = (const float*)d_in[21];
    const float* w_o3    = (const float*)d_in[22];
    const float* b_o3    = (const float*)d_in[23];

    float *h, *hn, *proj, *ut, *ssmb, *dtb, *yb, *f1, *f2, *o1b, *o2b;
    cudaGetSymbolAddress((void**)&h,    g_h);
    cudaGetSymbolAddress((void**)&hn,   g_hn);
    cudaGetSymbolAddress((void**)&proj, g_proj);
    cudaGetSymbolAddress((void**)&ut,   g_ut);
    cudaGetSymbolAddress((void**)&ssmb, g_ssm);
    cudaGetSymbolAddress((void**)&dtb,  g_dt);
    cudaGetSymbolAddress((void**)&yb,   g_y);
    cudaGetSymbolAddress((void**)&f1,   g_f1);
    cudaGetSymbolAddress((void**)&f2,   g_f2);
    cudaGetSymbolAddress((void**)&o1b,  g_o1);
    cudaGetSymbolAddress((void**)&o2b,  g_o2);

    dim3 blk256(256), blk128(128);

    // ---- input MLP (fp32, runs once) ----
    gemm_k<1, true><<<dim3(4, 8, 1), blk256>>>(
        x, Fin, w_in1, 256, b_in1, f1, 256, Msz, 256, Fin);
    gemm_k<1, true><<<dim3(4, 8, 1), blk256>>>(
        f1, 256, w_in2, 256, b_in2, f2, 256, Msz, 256, 256);
    gemm_k<0, true><<<dim3(12, 8, 1), blk256>>>(
        f2, 256, w_in3, Dm, b_in3, h, Dm, Msz, Dm, 256);

    // ---- 32 mamba layers ----
    for (int l = 0; l < NL; l++) {
        const float* nw_l  = norm_w + (size_t)l * Dm;
        const float* ipw_l = ipw    + (size_t)l * Dm * PROJ2;
        const float* cw_l  = cw     + (size_t)l * Isz * Kcv;
        const float* cb_l  = cb     + (size_t)l * Isz;
        const float* xpw_l = xpw    + (size_t)l * Isz * 80;
        const float* dpw_l = dpw    + (size_t)l * Rlr * Isz;
        const float* dpb_l = dpb    + (size_t)l * Isz;
        const float* al_l  = alog   + (size_t)l * Isz * Nst;
        const float* dp_l  = dprm   + (size_t)l * Isz;
        const float* opw_l = opw    + (size_t)l * Isz * Dm;

        rmsnorm_k<<<Msz, blk256>>>(h, nw_l, hn, Dm);

        // in_proj: [480,768] x [768,3072]
        mma_gemm_k<0, false, false><<<dim3(48, 8, 1), blk128>>>(
            hn, Dm, ipw_l, PROJ2, nullptr, proj, PROJ2, Msz, PROJ2, Dm);

        conv_silu_k<<<(Msz * Isz + 255) / 256, blk256>>>(proj, cw_l, cb_l, ut);

        // x_proj: [480,1536] x [1536,80], split-K=8 with atomics
        cudaMemsetAsync(ssmb, 0, (size_t)Msz * 80 * sizeof(float));
        mma_gemm_k<0, false, true><<<dim3(2, 8, 8), blk128>>>(
            ut, Isz, xpw_l, 80, nullptr, ssmb, 80, Msz, 80, Isz);

        // dt_proj: [480,48] x [48,1536], softplus + bias
        mma_gemm_k<2, true, false><<<dim3(24, 8, 1), blk128>>>(
            ssmb, 80, dpw_l, Isz, dpb_l, dtb, Isz, Msz, Isz, Rlr);

        scan_k<<<dim3(Isz / 128, Bsz), blk128>>>(ssmb, dtb, ut, proj, al_l, dp_l, yb);

        // out_proj: [480,1536] x [1536,768], split-K=2, atomic residual add into h
        mma_gemm_k<0, false, true><<<dim3(12, 8, 2), blk128>>>(
            yb, Isz, opw_l, Dm, nullptr, h, Dm, Msz, Dm, Isz);
    }

    // ---- final norm + output head ----
    rmsnorm_k<<<Msz, blk256>>>(h, norm_fw, hn, Dm);
    rk_gemm_k<<<dim3(8, Bsz), blk256>>>(hn, Dm * Lsz, w_o1, 256, b_o1, o1b, 256, Dm * Lsz, 1);
    rk_gemm_k<<<dim3(8, Bsz), blk256>>>(o1b, 256, w_o2, 256, b_o2, o2b, 256, 256, 1);
    out3_k<<<Bsz, blk256>>>(o2b, w_o3, b_o3, (float*)d_out);
}

// round 5
// speedup vs baseline: 1.3165x; 1.1450x over previous
#include <cuda_runtime.h>
#include <cuda_bf16.h>
#include <math.h>
#include <stdint.h>

// ---------------- problem constants ----------------
#define Bsz 8
#define Lsz 60
#define Msz (Bsz * Lsz)      // 480 rows
#define Fin 13
#define Dm  768
#define Isz 1536
#define Nst 16
#define Rlr 48
#define Kcv 4
#define NL  32
#define PROJ2 (2 * Isz)      // 3072

// ---------------- scratch (device globals, no allocation) ----------------
__device__ float g_h   [Msz * Dm];
__device__ float g_hn  [Msz * Dm];
__device__ float g_proj[Msz * PROJ2];
__device__ float g_ut  [Msz * Isz];
__device__ float g_ssm [Msz * 80];
__device__ float g_dt  [Msz * Isz];
__device__ float g_y   [Msz * Isz];
__device__ float g_f1  [Msz * 256];
__device__ float g_f2  [Msz * 256];
__device__ float g_o1  [Bsz * 256];
__device__ float g_o2  [Bsz * 256];

// ======================================================================
// 3xTF32 tensor-core GEMM, fragment-permuted smem, software-pipelined:
// registers prefetch chunk k+1 while chunk k computes.
// block tile 64x64, BK=32, 128 threads (4 warps 2x2), warp tile 32x32.
// ACT: 0 none, 1 relu, 2 softplus. ATOMIC => atomicAdd (split-K/residual).
// ======================================================================
__device__ __forceinline__ uint32_t f2tf(float f) {
    uint32_t u;
    asm("cvt.rna.tf32.f32 %0, %1;" : "=r"(u) : "f"(f));
    return u;
}

__device__ __forceinline__ void tf32_split(float v, uint32_t& hi, uint32_t& lo) {
    hi = f2tf(v);
    float r = v - __uint_as_float(hi);
    lo = f2tf(r);
}

__device__ __forceinline__ void mma_tf32(float c[4],
                                         uint32_t a0, uint32_t a1, uint32_t a2, uint32_t a3,
                                         uint32_t b0, uint32_t b1) {
    asm volatile(
        "mma.sync.aligned.m16n8k8.row.col.f32.tf32.tf32.f32 "
        "{%0,%1,%2,%3},{%4,%5,%6,%7},{%8,%9},{%0,%1,%2,%3};"
        : "+f"(c[0]), "+f"(c[1]), "+f"(c[2]), "+f"(c[3])
        : "r"(a0), "r"(a1), "r"(a2), "r"(a3), "r"(b0), "r"(b1));
}

template<int ACT, bool BIAS, bool ATOMIC>
__global__ void __launch_bounds__(128)
mma_gemm_k(const float* __restrict__ A, int lda,
           const float* __restrict__ B, int ldb,
           const float* __restrict__ bias,
           float* __restrict__ C, int ldc,
           int M, int N, int K)
{
    __shared__ uint4 AsPH[512];
    __shared__ uint4 AsPL[512];
    __shared__ uint4 BsPH[512];
    __shared__ uint4 BsPL[512];

    const int tid  = threadIdx.x;
    const int lane = tid & 31;
    const int warp = tid >> 5;
    const int warp_m = warp >> 1;
    const int warp_n = warp & 1;
    const int group = lane >> 2;
    const int tig   = lane & 3;

    const int m0 = blockIdx.y * 64;
    const int n0 = blockIdx.x * 64;

    int kchunk = (K + gridDim.z - 1) / gridDim.z;
    int k_beg  = blockIdx.z * kchunk;
    int k_end  = min(K, k_beg + kchunk);

    uint32_t* wAH = (uint32_t*)AsPH;
    uint32_t* wAL = (uint32_t*)AsPL;
    uint32_t* wBH = (uint32_t*)BsPH;
    uint32_t* wBL = (uint32_t*)BsPL;

    float acc[2][4][4];
    #pragma unroll
    for (int i = 0; i < 2; i++)
        #pragma unroll
        for (int j = 0; j < 4; j++)
            #pragma unroll
            for (int q = 0; q < 4; q++)
                acc[i][j][q] = 0.f;

    // staging registers (prefetch buffer)
    float ra[16], rb[16];

    auto load_chunk = [&](int k0) {
        const int kw = min(32, k_end - k0);
        #pragma unroll
        for (int it = 0; it < 16; ++it) {
            int idx = tid + it * 128;
            int m = idx >> 5, k = idx & 31;
            ra[it] = (m0 + m < M && k < kw) ? __ldg(&A[(size_t)(m0 + m) * lda + k0 + k]) : 0.f;
        }
        #pragma unroll
        for (int it = 0; it < 16; ++it) {
            int idx = tid + it * 128;
            int k = idx >> 6, n = idx & 63;
            rb[it] = (k < kw && n0 + n < N) ? __ldg(&B[(size_t)(k0 + k) * ldb + n0 + n]) : 0.f;
        }
    };

    load_chunk(k_beg);

    for (int k0 = k_beg; k0 < k_end; k0 += 32) {
        // ---- scatter prefetched regs into fragment-permuted smem ----
        #pragma unroll
        for (int it = 0; it < 16; ++it) {
            int idx = tid + it * 128;
            int m = idx >> 5, k = idx & 31;
            uint32_t hi, lo; tf32_split(ra[it], hi, lo);
            int slot = ((((m >> 5) * 2 + ((m >> 4) & 1)) * 4 + (k >> 3)) * 32
                        + (m & 7) * 4 + (k & 3)) * 4
                       + ((m >> 3) & 1) + ((k >> 2) & 1) * 2;
            wAH[slot] = hi; wAL[slot] = lo;
        }
        #pragma unroll
        for (int it = 0; it < 16; ++it) {
            int idx = tid + it * 128;
            int k = idx >> 6, n = idx & 63;
            uint32_t hi, lo; tf32_split(rb[it], hi, lo);
            int slot = ((((n >> 5) * 4 + (k >> 3)) * 2 + ((n >> 4) & 1)) * 32
                        + (n & 7) * 4 + (k & 3)) * 4
                       + ((n >> 3) & 1) * 2 + ((k >> 2) & 1);
            wBH[slot] = hi; wBL[slot] = lo;
        }
        __syncthreads();

        // ---- prefetch NEXT chunk while this one computes ----
        if (k0 + 32 < k_end) load_chunk(k0 + 32);

        #pragma unroll
        for (int ks = 0; ks < 4; ks++) {
            uint4 aH[2], aL[2];
            #pragma unroll
            for (int i = 0; i < 2; i++) {
                int base = ((warp_m * 2 + i) * 4 + ks) * 32 + lane;
                aH[i] = AsPH[base];
                aL[i] = AsPL[base];
            }
            uint4 bH[2], bL[2];
            #pragma unroll
            for (int p = 0; p < 2; p++) {
                int base = ((warp_n * 4 + ks) * 2 + p) * 32 + lane;
                bH[p] = BsPH[base];
                bL[p] = BsPL[base];
            }
            #pragma unroll
            for (int i = 0; i < 2; i++) {
                #pragma unroll
                for (int j = 0; j < 4; j++) {
                    int p = j >> 1;
                    uint32_t b0H = (j & 1) ? ((p ? bH[1].z : bH[0].z)) : ((p ? bH[1].x : bH[0].x));
                    uint32_t b1H = (j & 1) ? ((p ? bH[1].w : bH[0].w)) : ((p ? bH[1].y : bH[0].y));
                    uint32_t b0L = (j & 1) ? ((p ? bL[1].z : bL[0].z)) : ((p ? bL[1].x : bL[0].x));
                    uint32_t b1L = (j & 1) ? ((p ? bL[1].w : bL[0].w)) : ((p ? bL[1].y : bL[0].y));
                    mma_tf32(acc[i][j], aL[i].x, aL[i].y, aL[i].z, aL[i].w, b0H, b1H);
                    mma_tf32(acc[i][j], aH[i].x, aH[i].y, aH[i].z, aH[i].w, b0L, b1L);
                    mma_tf32(acc[i][j], aH[i].x, aH[i].y, aH[i].z, aH[i].w, b0H, b1H);
                }
            }
        }
        __syncthreads();
    }

    // epilogue
    #pragma unroll
    for (int i = 0; i < 2; i++) {
        #pragma unroll
        for (int j = 0; j < 4; j++) {
            int row = m0 + warp_m * 32 + i * 16 + group;
            int col = n0 + warp_n * 32 + j * 8 + tig * 2;
            #pragma unroll
            for (int q = 0; q < 4; q++) {
                int r = row + (q >> 1) * 8;
                int c = col + (q & 1);
                if (r >= M || c >= N) continue;
                float v = acc[i][j][q];
                if (BIAS) v += bias[c];
                if (ACT == 1) v = fmaxf(v, 0.f);
                if (ACT == 2) v = (v > 20.f) ? v : log1pf(__expf(v));
                size_t idx = (size_t)r * ldc + c;
                if (ATOMIC) atomicAdd(&C[idx], v);
                else        C[idx] = v;
            }
        }
    }
}

// ---------------- fp32 fallback GEMM (input MLP, runs once) ----------------
#define BM 64
#define BN 64
#define BKt 16

template<int ACT, bool BIAS>
__global__ void gemm_k(const float* __restrict__ A, int lda,
                       const float* __restrict__ B, int ldb,
                       const float* __restrict__ bias,
                       float* __restrict__ C, int ldc,
                       int M, int N, int K)
{
    __shared__ float As[BKt][BM];
    __shared__ float Bs[BKt][BN];
    const int tid = threadIdx.x;
    const int tx = tid & 15, ty = tid >> 4;
    const int m0 = blockIdx.y * BM, n0 = blockIdx.x * BN;

    float acc[4][4] = {};
    const int la_m = tid >> 2;
    const int la_k = (tid & 3) * 4;
    const int lb_k = tid >> 4;
    const int lb_n = (tid & 15) * 4;

    for (int k0 = 0; k0 < K; k0 += BKt) {
        #pragma unroll
        for (int j = 0; j < 4; j++) {
            int m = m0 + la_m, k = k0 + la_k + j;
            As[la_k + j][la_m] = (m < M && k < K) ? A[(size_t)m * lda + k] : 0.f;
        }
        #pragma unroll
        for (int j = 0; j < 4; j++) {
            int k = k0 + lb_k, n = n0 + lb_n + j;
            Bs[lb_k][lb_n + j] = (k < K && n < N) ? B[(size_t)k * ldb + n] : 0.f;
        }
        __syncthreads();
        #pragma unroll
        for (int kk = 0; kk < BKt; kk++) {
            float4 ra = *reinterpret_cast<const float4*>(&As[kk][ty * 4]);
            float4 rb = *reinterpret_cast<const float4*>(&Bs[kk][tx * 4]);
            float a4[4] = {ra.x, ra.y, ra.z, ra.w};
            float b4[4] = {rb.x, rb.y, rb.z, rb.w};
            #pragma unroll
            for (int i = 0; i < 4; i++)
                #pragma unroll
                for (int j = 0; j < 4; j++)
                    acc[i][j] = fmaf(a4[i], b4[j], acc[i][j]);
        }
        __syncthreads();
    }

    #pragma unroll
    for (int i = 0; i < 4; i++) {
        int m = m0 + ty * 4 + i;
        if (m >= M) continue;
        #pragma unroll
        for (int j = 0; j < 4; j++) {
            int n = n0 + tx * 4 + j;
            if (n >= N) continue;
            float v = acc[i][j];
            if (BIAS) v += bias[n];
            if (ACT == 1) v = fmaxf(v, 0.f);
            C[(size_t)m * ldc + n] = v;
        }
    }
}

// ---------------- RMSNorm ----------------
__global__ void rmsnorm_k(const float* __restrict__ x, const float* __restrict__ w,
                          float* __restrict__ out, int D)
{
    int row = blockIdx.x;
    const float* xr = x + (size_t)row * D;
    float ss = 0.f;
    for (int d = threadIdx.x; d < D; d += blockDim.x) { float v = xr[d]; ss += v * v; }
    __shared__ float sm[32];
    for (int o = 16; o; o >>= 1) ss += __shfl_down_sync(0xffffffffu, ss, o);
    if ((threadIdx.x & 31) == 0) sm[threadIdx.x >> 5] = ss;
    __syncthreads();
    if (threadIdx.x < 32) {
        float v = (threadIdx.x < ((blockDim.x + 31) >> 5)) ? sm[threadIdx.x] : 0.f;
        for (int o = 16; o; o >>= 1) v += __shfl_down_sync(0xffffffffu, v, o);
        if (threadIdx.x == 0) sm[0] = v;
    }
    __syncthreads();
    float scale = rsqrtf(sm[0] / (float)D + 1e-5f);
    float* orow = out + (size_t)row * D;
    for (int d = threadIdx.x; d < D; d += blockDim.x) orow[d] = xr[d] * scale * w[d];
}

// ---------------- causal depthwise conv (K=4) + SiLU ----------------
__global__ void conv_silu_k(const float* __restrict__ proj,
                            const float* __restrict__ cw,
                            const float* __restrict__ cb,
                            float* __restrict__ ut)
{
    int gid = blockIdx.x * blockDim.x + threadIdx.x;
    if (gid >= Msz * Isz) return;
    int i = gid % Isz;
    int row = gid / Isz;
    int t = row % Lsz;
    float w0 = cw[i * 4 + 0], w1 = cw[i * 4 + 1], w2 = cw[i * 4 + 2], w3 = cw[i * 4 + 3];
    float acc = cb[i];
    const float* base = proj + (size_t)row * PROJ2 + i;
    if (t >= 3) acc = fmaf(w0, base[-3 * PROJ2], acc);
    if (t >= 2) acc = fmaf(w1, base[-2 * PROJ2], acc);
    if (t >= 1) acc = fmaf(w2, base[-1 * PROJ2], acc);
    acc = fmaf(w3, base[0], acc);
    ut[gid] = acc / (1.f + __expf(-acc));
}

// ---------------- selective-scan + D skip + gate ----------------
__global__ void __launch_bounds__(128)
scan_k(const float* __restrict__ ssm,
       const float* __restrict__ dt,
       const float* __restrict__ ut,
       const float* __restrict__ proj,
       const float* __restrict__ A_log,
       const float* __restrict__ Dp,
       float* __restrict__ y)
{
    int b = blockIdx.y;
    int ci = blockIdx.x * blockDim.x + threadIdx.x;
    __shared__ float sB[Lsz][Nst], sC[Lsz][Nst];
    for (int q = threadIdx.x; q < Lsz * 32; q += blockDim.x) {
        int t = q >> 5, c = q & 31;
        float v = ssm[(size_t)(b * Lsz + t) * 80 + 48 + c];
        if (c < Nst) sB[t][c] = v; else sC[t][c - Nst] = v;
    }
    __syncthreads();

    float a[Nst];
    #pragma unroll
    for (int n = 0; n < Nst; n++) a[n] = -__expf(A_log[(size_t)ci * Nst + n]);
    float Dv = Dp[ci];
    float s[Nst];
    #pragma unroll
    for (int n = 0; n < Nst; n++) s[n] = 0.f;

    for (int t = 0; t < Lsz; t++) {
        size_t row = (size_t)b * Lsz + t;
        float dtv = dt[row * Isz + ci];
        float uv  = ut[row * Isz + ci];
        float du  = dtv * uv;
        float acc = 0.f;
        #pragma unroll
        for (int n = 0; n < Nst; n++) {
            float dA = __expf(dtv * a[n]);
            s[n] = fmaf(dA, s[n], du * sB[t][n]);
            acc = fmaf(s[n], sC[t][n], acc);
        }
        float g = proj[row * PROJ2 + Isz + ci];
        float sig = 1.f / (1.f + __expf(-g));
        y[row * Isz + ci] = (acc + uv * Dv) * (g * sig);
    }
}

// ---------------- reduction GEMM for tiny-M output head ----------------
__global__ void rk_gemm_k(const float* __restrict__ A, int lda,
                          const float* __restrict__ B, int ldb,
                          const float* __restrict__ bias,
                          float* __restrict__ C, int N, int K, int relu)
{
    int lane = threadIdx.x & 31;
    int kg = threadIdx.x >> 5;
    int n = blockIdx.x * 32 + lane;
    int m = blockIdx.y;
    float acc = 0.f;
    if (n < N) {
        const float* arow = A + (size_t)m * lda;
        for (int k = kg; k < K; k += 8)
            acc = fmaf(arow[k], B[(size_t)k * ldb + n], acc);
    }
    __shared__ float sm[256];
    sm[threadIdx.x] = acc;
    __syncthreads();
    if (kg == 0 && n < N) {
        float v = acc;
        #pragma unroll
        for (int g2 = 1; g2 < 8; g2++) v += sm[g2 * 32 + lane];
        v += bias[n];
        if (relu) v = fmaxf(v, 0.f);
        C[(size_t)m * N + n] = v;
    }
}

// ---------------- final dot ----------------
__global__ void out3_k(const float* __restrict__ o2, const float* __restrict__ w,
                       const float* __restrict__ bb, float* __restrict__ out)
{
    int m = blockIdx.x;
    int tid = threadIdx.x;
    float v = o2[m * 256 + tid] * w[tid];
    for (int o = 16; o; o >>= 1) v += __shfl_down_sync(0xffffffffu, v, o);
    __shared__ float sm[8];
    if ((tid & 31) == 0) sm[tid >> 5] = v;
    __syncthreads();
    if (tid == 0) {
        float t = 0.f;
        #pragma unroll
        for (int g = 0; g < 8; g++) t += sm[g];
        out[m] = t + bb[0];
    }
}

// ---------------- host orchestration ----------------
extern "C" void kernel_launch(void* const* d_in, const int* in_sizes, int n_in,
                              void* d_out, int out_size)
{
    const float* x       = (const float*)d_in[0];
    const float* w_in1   = (const float*)d_in[1];
    const float* b_in1   = (const float*)d_in[2];
    const float* w_in2   = (const float*)d_in[3];
    const float* b_in2   = (const float*)d_in[4];
    const float* w_in3   = (const float*)d_in[5];
    const float* b_in3   = (const float*)d_in[6];
    const float* norm_w  = (const float*)d_in[7];
    const float* ipw     = (const float*)d_in[8];
    const float* cw      = (const float*)d_in[9];
    const float* cb      = (const float*)d_in[10];
    const float* xpw     = (const float*)d_in[11];
    const float* dpw     = (const float*)d_in[12];
    const float* dpb     = (const float*)d_in[13];
    const float* alog    = (const float*)d_in[14];
    const float* dprm    = (const float*)d_in[15];
    const float* opw     = (const float*)d_in[16];
    const float* norm_fw = (const float*)d_in[17];
    const float* w_o1    = (const float*)d_in[18];
    const float* b_o1    = (const float*)d_in[19];
    const float* w_o2    = (const float*)d_in[20];
    const float* b_o2    = (const float*)d_in[21];
    const float* w_o3    = (const float*)d_in[22];
    const float* b_o3    = (const float*)d_in[23];

    float *h, *hn, *proj, *ut, *ssmb, *dtb, *yb, *f1, *f2, *o1b, *o2b;
    cudaGetSymbolAddress((void**)&h,    g_h);
    cudaGetSymbolAddress((void**)&hn,   g_hn);
    cudaGetSymbolAddress((void**)&proj, g_proj);
    cudaGetSymbolAddress((void**)&ut,   g_ut);
    cudaGetSymbolAddress((void**)&ssmb, g_ssm);
    cudaGetSymbolAddress((void**)&dtb,  g_dt);
    cudaGetSymbolAddress((void**)&yb,   g_y);
    cudaGetSymbolAddress((void**)&f1,   g_f1);
    cudaGetSymbolAddress((void**)&f2,   g_f2);
    cudaGetSymbolAddress((void**)&o1b,  g_o1);
    cudaGetSymbolAddress((void**)&o2b,  g_o2);

    dim3 blk256(256), blk128(128);

    // ---- input MLP (fp32, runs once) ----
    gemm_k<1, true><<<dim3(4, 8, 1), blk256>>>(
        x, Fin, w_in1, 256, b_in1, f1, 256, Msz, 256, Fin);
    gemm_k<1, true><<<dim3(4, 8, 1), blk256>>>(
        f1, 256, w_in2, 256, b_in2, f2, 256, Msz, 256, 256);
    gemm_k<0, true><<<dim3(12, 8, 1), blk256>>>(
        f2, 256, w_in3, Dm, b_in3, h, Dm, Msz, Dm, 256);

    // ---- 32 mamba layers ----
    for (int l = 0; l < NL; l++) {
        const float* nw_l  = norm_w + (size_t)l * Dm;
        const float* ipw_l = ipw    + (size_t)l * Dm * PROJ2;
        const float* cw_l  = cw     + (size_t)l * Isz * Kcv;
        const float* cb_l  = cb     + (size_t)l * Isz;
        const float* xpw_l = xpw    + (size_t)l * Isz * 80;
        const float* dpw_l = dpw    + (size_t)l * Rlr * Isz;
        const float* dpb_l = dpb    + (size_t)l * Isz;
        const float* al_l  = alog   + (size_t)l * Isz * Nst;
        const float* dp_l  = dprm   + (size_t)l * Isz;
        const float* opw_l = opw    + (size_t)l * Isz * Dm;

        rmsnorm_k<<<Msz, blk256>>>(h, nw_l, hn, Dm);

        // in_proj: [480,768] x [768,3072], split-K=2 + atomics (zeroed first)
        cudaMemsetAsync(proj, 0, (size_t)Msz * PROJ2 * sizeof(float));
        mma_gemm_k<0, false, true><<<dim3(48, 8, 2), blk128>>>(
            hn, Dm, ipw_l, PROJ2, nullptr, proj, PROJ2, Msz, PROJ2, Dm);

        conv_silu_k<<<(Msz * Isz + 255) / 256, blk256>>>(proj, cw_l, cb_l, ut);

        // x_proj: [480,1536] x [1536,80], split-K=8 with atomics
        cudaMemsetAsync(ssmb, 0, (size_t)Msz * 80 * sizeof(float));
        mma_gemm_k<0, false, true><<<dim3(2, 8, 8), blk128>>>(
            ut, Isz, xpw_l, 80, nullptr, ssmb, 80, Msz, 80, Isz);

        // dt_proj: [480,48] x [48,1536], softplus + bias
        mma_gemm_k<2, true, false><<<dim3(24, 8, 1), blk128>>>(
            ssmb, 80, dpw_l, Isz, dpb_l, dtb, Isz, Msz, Isz, Rlr);

        scan_k<<<dim3(Isz / 128, Bsz), blk128>>>(ssmb, dtb, ut, proj, al_l, dp_l, yb);

        // out_proj: [480,1536] x [1536,768], split-K=2, atomic residual add into h
        mma_gemm_k<0, false, true><<<dim3(12, 8, 2), blk128>>>(
            yb, Isz, opw_l, Dm, nullptr, h, Dm, Msz, Dm, Isz);
    }

    // ---- final norm + output head ----
    rmsnorm_k<<<Msz, blk256>>>(h, norm_fw, hn, Dm);
    rk_gemm_k<<<dim3(8, Bsz), blk256>>>(hn, Dm * Lsz, w_o1, 256, b_o1, o1b, 256, Dm * Lsz, 1);
    rk_gemm_k<<<dim3(8, Bsz), blk256>>>(o1b, 256, w_o2, 256, b_o2, o2b, 256, 256, 1);
    out3_k<<<Bsz, blk256>>>(o2b, w_o3, b_o3, (float*)d_out);
}

// round 6
// speedup vs baseline: 1.7143x; 1.3022x over previous
#include <cuda_runtime.h>
#include <cuda_bf16.h>
#include <math.h>
#include <stdint.h>

// ---------------- problem constants ----------------
#define Bsz 8
#define Lsz 60
#define Msz (Bsz * Lsz)      // 480 rows
#define Fin 13
#define Dm  768
#define Isz 1536
#define Nst 16
#define Rlr 48
#define Kcv 4
#define NL  32
#define PROJ2 (2 * Isz)      // 3072

// ---------------- scratch (device globals, no allocation) ----------------
__device__ float g_h   [Msz * Dm];
__device__ float g_hn  [Msz * Dm];
__device__ float g_proj[Msz * PROJ2];
__device__ float g_ut  [Msz * Isz];
__device__ float g_ssm [Msz * 80];
__device__ float g_dt  [Msz * Isz];
__device__ float g_y   [Msz * Isz];
__device__ float g_f1  [Msz * 256];
__device__ float g_f2  [Msz * 256];
__device__ float g_o1  [Bsz * 256];
__device__ float g_o2  [Bsz * 256];

// ======================================================================
// bf16x3 tensor-core GEMM (m16n8k16), fragment-permuted smem, pipelined.
// v = hi + lo (both bf16); acc += hi*lo + lo*hi + hi*hi  (fp32 accum).
// block tile 64x64, BK=32, 128 threads (4 warps 2x2), warp tile 32x32.
// ACT: 0 none, 1 relu, 2 softplus. ATOMIC => atomicAdd (split-K/residual).
// ======================================================================
__device__ __forceinline__ void bf16x2_split(float v0, float v1,
                                             uint32_t& hi, uint32_t& lo) {
    __nv_bfloat16 h0 = __float2bfloat16_rn(v0);
    __nv_bfloat16 h1 = __float2bfloat16_rn(v1);
    float r0 = v0 - __bfloat162float(h0);
    float r1 = v1 - __bfloat162float(h1);
    __nv_bfloat16 l0 = __float2bfloat16_rn(r0);
    __nv_bfloat16 l1 = __float2bfloat16_rn(r1);
    hi = ((uint32_t)__bfloat16_as_ushort(h1) << 16) | __bfloat16_as_ushort(h0);
    lo = ((uint32_t)__bfloat16_as_ushort(l1) << 16) | __bfloat16_as_ushort(l0);
}

__device__ __forceinline__ void mma_bf16(float c[4],
                                         uint32_t a0, uint32_t a1, uint32_t a2, uint32_t a3,
                                         uint32_t b0, uint32_t b1) {
    asm volatile(
        "mma.sync.aligned.m16n8k16.row.col.f32.bf16.bf16.f32 "
        "{%0,%1,%2,%3},{%4,%5,%6,%7},{%8,%9},{%0,%1,%2,%3};"
        : "+f"(c[0]), "+f"(c[1]), "+f"(c[2]), "+f"(c[3])
        : "r"(a0), "r"(a1), "r"(a2), "r"(a3), "r"(b0), "r"(b1));
}

template<int ACT, bool BIAS, bool ATOMIC>
__global__ void __launch_bounds__(128)
mma_gemm_k(const float* __restrict__ A, int lda,
           const float* __restrict__ B, int ldb,
           const float* __restrict__ bias,
           float* __restrict__ C, int ldc,
           int M, int N, int K)
{
    // A fragments: [wm(2)][i(2)][ks(2)][lane(32)] uint4 (a0..a3 bf16x2)
    // B fragments: [wn(2)][ks(2)][pair(2)][lane(32)] uint4
    __shared__ uint4 AsPH[256];
    __shared__ uint4 AsPL[256];
    __shared__ uint4 BsPH[256];
    __shared__ uint4 BsPL[256];

    const int tid  = threadIdx.x;
    const int lane = tid & 31;
    const int warp = tid >> 5;
    const int warp_m = warp >> 1;
    const int warp_n = warp & 1;
    const int group = lane >> 2;
    const int tig   = lane & 3;

    const int m0 = blockIdx.y * 64;
    const int n0 = blockIdx.x * 64;

    int kchunk = (K + gridDim.z - 1) / gridDim.z;
    int k_beg  = blockIdx.z * kchunk;
    int k_end  = min(K, k_beg + kchunk);

    uint32_t* wAH = (uint32_t*)AsPH;
    uint32_t* wAL = (uint32_t*)AsPL;
    uint32_t* wBH = (uint32_t*)BsPH;
    uint32_t* wBL = (uint32_t*)BsPL;

    float acc[2][4][4];
    #pragma unroll
    for (int i = 0; i < 2; i++)
        #pragma unroll
        for (int j = 0; j < 4; j++)
            #pragma unroll
            for (int q = 0; q < 4; q++)
                acc[i][j][q] = 0.f;

    // prefetch registers: A 8 k-pairs, B 8 (k-pair, n) entries
    float2 ra[8], rb[8];

    auto load_chunk = [&](int k0) {
        const int kw = k_end - k0;   // multiple of 16 except possibly last-overall (still mult of 16 here)
        #pragma unroll
        for (int it = 0; it < 8; ++it) {
            int s = tid + it * 128;        // 0..1023
            int m = s >> 4, kp = s & 15;   // k = 2*kp
            float2 v = make_float2(0.f, 0.f);
            if (m0 + m < M && 2 * kp < kw)
                v = *reinterpret_cast<const float2*>(&A[(size_t)(m0 + m) * lda + k0 + 2 * kp]);
            ra[it] = v;
        }
        #pragma unroll
        for (int it = 0; it < 8; ++it) {
            int s = tid + it * 128;
            int kp = s >> 6, n = s & 63;   // k = 2*kp
            float2 v = make_float2(0.f, 0.f);
            if (n0 + n < N && 2 * kp < kw) {
                const float* p = &B[(size_t)(k0 + 2 * kp) * ldb + n0 + n];
                v.x = __ldg(p);
                v.y = __ldg(p + ldb);
            }
            rb[it] = v;
        }
    };

    load_chunk(k_beg);

    for (int k0 = k_beg; k0 < k_end; k0 += 32) {
        // ---- scatter prefetched regs into fragment-permuted smem ----
        #pragma unroll
        for (int it = 0; it < 8; ++it) {
            int s = tid + it * 128;
            int m = s >> 4, kp = s & 15;
            uint32_t hi, lo; bf16x2_split(ra[it].x, ra[it].y, hi, lo);
            int word = ((((m >> 5) * 2 + ((m >> 4) & 1)) * 2 + (kp >> 3)) * 32
                        + (m & 7) * 4 + (kp & 3)) * 4
                       + ((m >> 3) & 1) + 2 * ((kp >> 2) & 1);
            wAH[word] = hi; wAL[word] = lo;
        }
        #pragma unroll
        for (int it = 0; it < 8; ++it) {
            int s = tid + it * 128;
            int kp = s >> 6, n = s & 63;
            uint32_t hi, lo; bf16x2_split(rb[it].x, rb[it].y, hi, lo);
            int word = ((((n >> 5) * 2 + (kp >> 3)) * 2 + ((n >> 4) & 1)) * 32
                        + (n & 7) * 4 + (kp & 3)) * 4
                       + ((n >> 3) & 1) * 2 + ((kp >> 2) & 1);
            wBH[word] = hi; wBL[word] = lo;
        }
        __syncthreads();

        // ---- prefetch NEXT chunk while this one computes ----
        if (k0 + 32 < k_end) load_chunk(k0 + 32);

        #pragma unroll
        for (int ks = 0; ks < 2; ks++) {
            uint4 aH[2], aL[2];
            #pragma unroll
            for (int i = 0; i < 2; i++) {
                int base = ((warp_m * 2 + i) * 2 + ks) * 32 + lane;
                aH[i] = AsPH[base];
                aL[i] = AsPL[base];
            }
            uint4 bH[2], bL[2];
            #pragma unroll
            for (int p = 0; p < 2; p++) {
                int base = ((warp_n * 2 + ks) * 2 + p) * 32 + lane;
                bH[p] = BsPH[base];
                bL[p] = BsPL[base];
            }
            #pragma unroll
            for (int i = 0; i < 2; i++) {
                #pragma unroll
                for (int j = 0; j < 4; j++) {
                    int p = j >> 1;
                    uint32_t b0H = (j & 1) ? ((p ? bH[1].z : bH[0].z)) : ((p ? bH[1].x : bH[0].x));
                    uint32_t b1H = (j & 1) ? ((p ? bH[1].w : bH[0].w)) : ((p ? bH[1].y : bH[0].y));
                    uint32_t b0L = (j & 1) ? ((p ? bL[1].z : bL[0].z)) : ((p ? bL[1].x : bL[0].x));
                    uint32_t b1L = (j & 1) ? ((p ? bL[1].w : bL[0].w)) : ((p ? bL[1].y : bL[0].y));
                    // lo-products first, hi*hi last
                    mma_bf16(acc[i][j], aH[i].x, aH[i].y, aH[i].z, aH[i].w, b0L, b1L);
                    mma_bf16(acc[i][j], aL[i].x, aL[i].y, aL[i].z, aL[i].w, b0H, b1H);
                    mma_bf16(acc[i][j], aH[i].x, aH[i].y, aH[i].z, aH[i].w, b0H, b1H);
                }
            }
        }
        __syncthreads();
    }

    // epilogue (m16n8 accumulator layout)
    #pragma unroll
    for (int i = 0; i < 2; i++) {
        #pragma unroll
        for (int j = 0; j < 4; j++) {
            int row = m0 + warp_m * 32 + i * 16 + group;
            int col = n0 + warp_n * 32 + j * 8 + tig * 2;
            #pragma unroll
            for (int q = 0; q < 4; q++) {
                int r = row + (q >> 1) * 8;
                int c = col + (q & 1);
                if (r >= M || c >= N) continue;
                float v = acc[i][j][q];
                if (BIAS) v += bias[c];
                if (ACT == 1) v = fmaxf(v, 0.f);
                if (ACT == 2) v = (v > 20.f) ? v : log1pf(__expf(v));
                size_t idx = (size_t)r * ldc + c;
                if (ATOMIC) atomicAdd(&C[idx], v);
                else        C[idx] = v;
            }
        }
    }
}

// ---------------- fp32 fallback GEMM (input MLP, runs once) ----------------
#define BM 64
#define BN 64
#define BKt 16

template<int ACT, bool BIAS>
__global__ void gemm_k(const float* __restrict__ A, int lda,
                       const float* __restrict__ B, int ldb,
                       const float* __restrict__ bias,
                       float* __restrict__ C, int ldc,
                       int M, int N, int K)
{
    __shared__ float As[BKt][BM];
    __shared__ float Bs[BKt][BN];
    const int tid = threadIdx.x;
    const int tx = tid & 15, ty = tid >> 4;
    const int m0 = blockIdx.y * BM, n0 = blockIdx.x * BN;

    float acc[4][4] = {};
    const int la_m = tid >> 2;
    const int la_k = (tid & 3) * 4;
    const int lb_k = tid >> 4;
    const int lb_n = (tid & 15) * 4;

    for (int k0 = 0; k0 < K; k0 += BKt) {
        #pragma unroll
        for (int j = 0; j < 4; j++) {
            int m = m0 + la_m, k = k0 + la_k + j;
            As[la_k + j][la_m] = (m < M && k < K) ? A[(size_t)m * lda + k] : 0.f;
        }
        #pragma unroll
        for (int j = 0; j < 4; j++) {
            int k = k0 + lb_k, n = n0 + lb_n + j;
            Bs[lb_k][lb_n + j] = (k < K && n < N) ? B[(size_t)k * ldb + n] : 0.f;
        }
        __syncthreads();
        #pragma unroll
        for (int kk = 0; kk < BKt; kk++) {
            float4 ra = *reinterpret_cast<const float4*>(&As[kk][ty * 4]);
            float4 rb = *reinterpret_cast<const float4*>(&Bs[kk][tx * 4]);
            float a4[4] = {ra.x, ra.y, ra.z, ra.w};
            float b4[4] = {rb.x, rb.y, rb.z, rb.w};
            #pragma unroll
            for (int i = 0; i < 4; i++)
                #pragma unroll
                for (int j = 0; j < 4; j++)
                    acc[i][j] = fmaf(a4[i], b4[j], acc[i][j]);
        }
        __syncthreads();
    }

    #pragma unroll
    for (int i = 0; i < 4; i++) {
        int m = m0 + ty * 4 + i;
        if (m >= M) continue;
        #pragma unroll
        for (int j = 0; j < 4; j++) {
            int n = n0 + tx * 4 + j;
            if (n >= N) continue;
            float v = acc[i][j];
            if (BIAS) v += bias[n];
            if (ACT == 1) v = fmaxf(v, 0.f);
            C[(size_t)m * ldc + n] = v;
        }
    }
}

// ---------------- RMSNorm ----------------
__global__ void rmsnorm_k(const float* __restrict__ x, const float* __restrict__ w,
                          float* __restrict__ out, int D)
{
    int row = blockIdx.x;
    const float* xr = x + (size_t)row * D;
    float ss = 0.f;
    for (int d = threadIdx.x; d < D; d += blockDim.x) { float v = xr[d]; ss += v * v; }
    __shared__ float sm[32];
    for (int o = 16; o; o >>= 1) ss += __shfl_down_sync(0xffffffffu, ss, o);
    if ((threadIdx.x & 31) == 0) sm[threadIdx.x >> 5] = ss;
    __syncthreads();
    if (threadIdx.x < 32) {
        float v = (threadIdx.x < ((blockDim.x + 31) >> 5)) ? sm[threadIdx.x] : 0.f;
        for (int o = 16; o; o >>= 1) v += __shfl_down_sync(0xffffffffu, v, o);
        if (threadIdx.x == 0) sm[0] = v;
    }
    __syncthreads();
    float scale = rsqrtf(sm[0] / (float)D + 1e-5f);
    float* orow = out + (size_t)row * D;
    for (int d = threadIdx.x; d < D; d += blockDim.x) orow[d] = xr[d] * scale * w[d];
}

// ---------------- causal depthwise conv (K=4) + SiLU ----------------
__global__ void conv_silu_k(const float* __restrict__ proj,
                            const float* __restrict__ cw,
                            const float* __restrict__ cb,
                            float* __restrict__ ut)
{
    int gid = blockIdx.x * blockDim.x + threadIdx.x;
    if (gid >= Msz * Isz) return;
    int i = gid % Isz;
    int row = gid / Isz;
    int t = row % Lsz;
    float w0 = cw[i * 4 + 0], w1 = cw[i * 4 + 1], w2 = cw[i * 4 + 2], w3 = cw[i * 4 + 3];
    float acc = cb[i];
    const float* base = proj + (size_t)row * PROJ2 + i;
    if (t >= 3) acc = fmaf(w0, base[-3 * PROJ2], acc);
    if (t >= 2) acc = fmaf(w1, base[-2 * PROJ2], acc);
    if (t >= 1) acc = fmaf(w2, base[-1 * PROJ2], acc);
    acc = fmaf(w3, base[0], acc);
    ut[gid] = acc / (1.f + __expf(-acc));
}

// ---------------- selective-scan + D skip + gate ----------------
__global__ void __launch_bounds__(128)
scan_k(const float* __restrict__ ssm,
       const float* __restrict__ dt,
       const float* __restrict__ ut,
       const float* __restrict__ proj,
       const float* __restrict__ A_log,
       const float* __restrict__ Dp,
       float* __restrict__ y)
{
    int b = blockIdx.y;
    int ci = blockIdx.x * blockDim.x + threadIdx.x;
    __shared__ float sB[Lsz][Nst], sC[Lsz][Nst];
    for (int q = threadIdx.x; q < Lsz * 32; q += blockDim.x) {
        int t = q >> 5, c = q & 31;
        float v = ssm[(size_t)(b * Lsz + t) * 80 + 48 + c];
        if (c < Nst) sB[t][c] = v; else sC[t][c - Nst] = v;
    }
    __syncthreads();

    float a[Nst];
    #pragma unroll
    for (int n = 0; n < Nst; n++) a[n] = -__expf(A_log[(size_t)ci * Nst + n]);
    float Dv = Dp[ci];
    float s[Nst];
    #pragma unroll
    for (int n = 0; n < Nst; n++) s[n] = 0.f;

    for (int t = 0; t < Lsz; t++) {
        size_t row = (size_t)b * Lsz + t;
        float dtv = dt[row * Isz + ci];
        float uv  = ut[row * Isz + ci];
        float du  = dtv * uv;
        float acc = 0.f;
        #pragma unroll
        for (int n = 0; n < Nst; n++) {
            float dA = __expf(dtv * a[n]);
            s[n] = fmaf(dA, s[n], du * sB[t][n]);
            acc = fmaf(s[n], sC[t][n], acc);
        }
        float g = proj[row * PROJ2 + Isz + ci];
        float sig = 1.f / (1.f + __expf(-g));
        y[row * Isz + ci] = (acc + uv * Dv) * (g * sig);
    }
}

// ---------------- reduction GEMM for tiny-M output head ----------------
__global__ void rk_gemm_k(const float* __restrict__ A, int lda,
                          const float* __restrict__ B, int ldb,
                          const float* __restrict__ bias,
                          float* __restrict__ C, int N, int K, int relu)
{
    int lane = threadIdx.x & 31;
    int kg = threadIdx.x >> 5;
    int n = blockIdx.x * 32 + lane;
    int m = blockIdx.y;
    float acc = 0.f;
    if (n < N) {
        const float* arow = A + (size_t)m * lda;
        for (int k = kg; k < K; k += 8)
            acc = fmaf(arow[k], B[(size_t)k * ldb + n], acc);
    }
    __shared__ float sm[256];
    sm[threadIdx.x] = acc;
    __syncthreads();
    if (kg == 0 && n < N) {
        float v = acc;
        #pragma unroll
        for (int g2 = 1; g2 < 8; g2++) v += sm[g2 * 32 + lane];
        v += bias[n];
        if (relu) v = fmaxf(v, 0.f);
        C[(size_t)m * N + n] = v;
    }
}

// ---------------- final dot ----------------
__global__ void out3_k(const float* __restrict__ o2, const float* __restrict__ w,
                       const float* __restrict__ bb, float* __restrict__ out)
{
    int m = blockIdx.x;
    int tid = threadIdx.x;
    float v = o2[m * 256 + tid] * w[tid];
    for (int o = 16; o; o >>= 1) v += __shfl_down_sync(0xffffffffu, v, o);
    __shared__ float sm[8];
    if ((tid & 31) == 0) sm[tid >> 5] = v;
    __syncthreads();
    if (tid == 0) {
        float t = 0.f;
        #pragma unroll
        for (int g = 0; g < 8; g++) t += sm[g];
        out[m] = t + bb[0];
    }
}

// ---------------- host orchestration ----------------
extern "C" void kernel_launch(void* const* d_in, const int* in_sizes, int n_in,
                              void* d_out, int out_size)
{
    const float* x       = (const float*)d_in[0];
    const float* w_in1   = (const float*)d_in[1];
    const float* b_in1   = (const float*)d_in[2];
    const float* w_in2   = (const float*)d_in[3];
    const float* b_in2   = (const float*)d_in[4];
    const float* w_in3   = (const float*)d_in[5];
    const float* b_in3   = (const float*)d_in[6];
    const float* norm_w  = (const float*)d_in[7];
    const float* ipw     = (const float*)d_in[8];
    const float* cw      = (const float*)d_in[9];
    const float* cb      = (const float*)d_in[10];
    const float* xpw     = (const float*)d_in[11];
    const float* dpw     = (const float*)d_in[12];
    const float* dpb     = (const float*)d_in[13];
    const float* alog    = (const float*)d_in[14];
    const float* dprm    = (const float*)d_in[15];
    const float* opw     = (const float*)d_in[16];
    const float* norm_fw = (const float*)d_in[17];
    const float* w_o1    = (const float*)d_in[18];
    const float* b_o1    = (const float*)d_in[19];
    const float* w_o2    = (const float*)d_in[20];
    const float* b_o2    = (const float*)d_in[21];
    const float* w_o3    = (const float*)d_in[22];
    const float* b_o3    = (const float*)d_in[23];

    float *h, *hn, *proj, *ut, *ssmb, *dtb, *yb, *f1, *f2, *o1b, *o2b;
    cudaGetSymbolAddress((void**)&h,    g_h);
    cudaGetSymbolAddress((void**)&hn,   g_hn);
    cudaGetSymbolAddress((void**)&proj, g_proj);
    cudaGetSymbolAddress((void**)&ut,   g_ut);
    cudaGetSymbolAddress((void**)&ssmb, g_ssm);
    cudaGetSymbolAddress((void**)&dtb,  g_dt);
    cudaGetSymbolAddress((void**)&yb,   g_y);
    cudaGetSymbolAddress((void**)&f1,   g_f1);
    cudaGetSymbolAddress((void**)&f2,   g_f2);
    cudaGetSymbolAddress((void**)&o1b,  g_o1);
    cudaGetSymbolAddress((void**)&o2b,  g_o2);

    dim3 blk256(256), blk128(128);

    // ---- input MLP (fp32, runs once) ----
    gemm_k<1, true><<<dim3(4, 8, 1), blk256>>>(
        x, Fin, w_in1, 256, b_in1, f1, 256, Msz, 256, Fin);
    gemm_k<1, true><<<dim3(4, 8, 1), blk256>>>(
        f1, 256, w_in2, 256, b_in2, f2, 256, Msz, 256, 256);
    gemm_k<0, true><<<dim3(12, 8, 1), blk256>>>(
        f2, 256, w_in3, Dm, b_in3, h, Dm, Msz, Dm, 256);

    // ---- 32 mamba layers ----
    for (int l = 0; l < NL; l++) {
        const float* nw_l  = norm_w + (size_t)l * Dm;
        const float* ipw_l = ipw    + (size_t)l * Dm * PROJ2;
        const float* cw_l  = cw     + (size_t)l * Isz * Kcv;
        const float* cb_l  = cb     + (size_t)l * Isz;
        const float* xpw_l = xpw    + (size_t)l * Isz * 80;
        const float* dpw_l = dpw    + (size_t)l * Rlr * Isz;
        const float* dpb_l = dpb    + (size_t)l * Isz;
        const float* al_l  = alog   + (size_t)l * Isz * Nst;
        const float* dp_l  = dprm   + (size_t)l * Isz;
        const float* opw_l = opw    + (size_t)l * Isz * Dm;

        rmsnorm_k<<<Msz, blk256>>>(h, nw_l, hn, Dm);

        // in_proj: [480,768] x [768,3072], split-K=2 + atomics (zeroed first)
        cudaMemsetAsync(proj, 0, (size_t)Msz * PROJ2 * sizeof(float));
        mma_gemm_k<0, false, true><<<dim3(48, 8, 2), blk128>>>(
            hn, Dm, ipw_l, PROJ2, nullptr, proj, PROJ2, Msz, PROJ2, Dm);

        conv_silu_k<<<(Msz * Isz + 255) / 256, blk256>>>(proj, cw_l, cb_l, ut);

        // x_proj: [480,1536] x [1536,80], split-K=8 with atomics
        cudaMemsetAsync(ssmb, 0, (size_t)Msz * 80 * sizeof(float));
        mma_gemm_k<0, false, true><<<dim3(2, 8, 8), blk128>>>(
            ut, Isz, xpw_l, 80, nullptr, ssmb, 80, Msz, 80, Isz);

        // dt_proj: [480,48] x [48,1536], softplus + bias
        mma_gemm_k<2, true, false><<<dim3(24, 8, 1), blk128>>>(
            ssmb, 80, dpw_l, Isz, dpb_l, dtb, Isz, Msz, Isz, Rlr);

        scan_k<<<dim3(Isz / 128, Bsz), blk128>>>(ssmb, dtb, ut, proj, al_l, dp_l, yb);

        // out_proj: [480,1536] x [1536,768], split-K=2, atomic residual add into h
        mma_gemm_k<0, false, true><<<dim3(12, 8, 2), blk128>>>(
            yb, Isz, opw_l, Dm, nullptr, h, Dm, Msz, Dm, Isz);
    }

    // ---- final norm + output head ----
    rmsnorm_k<<<Msz, blk256>>>(h, norm_fw, hn, Dm);
    rk_gemm_k<<<dim3(8, Bsz), blk256>>>(hn, Dm * Lsz, w_o1, 256, b_o1, o1b, 256, Dm * Lsz, 1);
    rk_gemm_k<<<dim3(8, Bsz), blk256>>>(o1b, 256, w_o2, 256, b_o2, o2b, 256, 256, 1);
    out3_k<<<Bsz, blk256>>>(o2b, w_o3, b_o3, (float*)d_out);
}

// round 8
// speedup vs baseline: 1.7847x; 1.0411x over previous
#include <cuda_runtime.h>
#include <cuda_bf16.h>
#include <math.h>
#include <stdint.h>

// ---------------- problem constants ----------------
#define Bsz 8
#define Lsz 60
#define Msz (Bsz * Lsz)      // 480 rows
#define Fin 13
#define Dm  768
#define Isz 1536
#define Nst 16
#define Rlr 48
#define Kcv 4
#define NL  32
#define PROJ2 (2 * Isz)      // 3072

// ---------------- scratch (device globals, no allocation) ----------------
__device__ float g_h   [Msz * Dm];
__device__ float g_hn  [Msz * Dm];
__device__ float g_proj[Msz * PROJ2];
__device__ float g_ut  [Msz * Isz];
__device__ float g_ssm [Msz * 80];
__device__ float g_y   [Msz * Isz];
__device__ float g_f1  [Msz * 256];
__device__ float g_f2  [Msz * 256];
__device__ float g_o1  [Bsz * 256];
__device__ float g_o2  [Bsz * 256];

// ======================================================================
// bf16x3 tensor-core GEMM (m16n8k16), fragment-permuted smem,
// DOUBLE-BUFFERED: compute(k) overlaps scatter(k+1) in one barrier interval.
// v = hi + lo (bf16); acc += hi*lo + lo*hi + hi*hi  (fp32 accum).
// block tile 64x64, BK=32, 128 threads (4 warps 2x2), warp tile 32x32.
// ACT: 0 none, 1 relu, 2 softplus. ATOMIC => atomicAdd (split-K/residual).
// ======================================================================
__device__ __forceinline__ void bf16x2_split(float v0, float v1,
                                             uint32_t& hi, uint32_t& lo) {
    __nv_bfloat16 h0 = __float2bfloat16_rn(v0);
    __nv_bfloat16 h1 = __float2bfloat16_rn(v1);
    float r0 = v0 - __bfloat162float(h0);
    float r1 = v1 - __bfloat162float(h1);
    __nv_bfloat16 l0 = __float2bfloat16_rn(r0);
    __nv_bfloat16 l1 = __float2bfloat16_rn(r1);
    hi = ((uint32_t)__bfloat16_as_ushort(h1) << 16) | __bfloat16_as_ushort(h0);
    lo = ((uint32_t)__bfloat16_as_ushort(l1) << 16) | __bfloat16_as_ushort(l0);
}

__device__ __forceinline__ void mma_bf16(float c[4],
                                         uint32_t a0, uint32_t a1, uint32_t a2, uint32_t a3,
                                         uint32_t b0, uint32_t b1) {
    asm volatile(
        "mma.sync.aligned.m16n8k16.row.col.f32.bf16.bf16.f32 "
        "{%0,%1,%2,%3},{%4,%5,%6,%7},{%8,%9},{%0,%1,%2,%3};"
        : "+f"(c[0]), "+f"(c[1]), "+f"(c[2]), "+f"(c[3])
        : "r"(a0), "r"(a1), "r"(a2), "r"(a3), "r"(b0), "r"(b1));
}

template<int ACT, bool BIAS, bool ATOMIC>
__global__ void __launch_bounds__(128)
mma_gemm_k(const float* __restrict__ A, int lda,
           const float* __restrict__ B, int ldb,
           const float* __restrict__ bias,
           float* __restrict__ C, int ldc,
           int M, int N, int K)
{
    // double-buffered fragment-permuted tiles
    __shared__ uint4 AsPH[2][256];
    __shared__ uint4 AsPL[2][256];
    __shared__ uint4 BsPH[2][256];
    __shared__ uint4 BsPL[2][256];

    const int tid  = threadIdx.x;
    const int lane = tid & 31;
    const int warp = tid >> 5;
    const int warp_m = warp >> 1;
    const int warp_n = warp & 1;
    const int group = lane >> 2;
    const int tig   = lane & 3;

    const int m0 = blockIdx.y * 64;
    const int n0 = blockIdx.x * 64;

    int kchunk = (K + gridDim.z - 1) / gridDim.z;
    int k_beg  = blockIdx.z * kchunk;
    int k_end  = min(K, k_beg + kchunk);

    float acc[2][4][4];
    #pragma unroll
    for (int i = 0; i < 2; i++)
        #pragma unroll
        for (int j = 0; j < 4; j++)
            #pragma unroll
            for (int q = 0; q < 4; q++)
                acc[i][j][q] = 0.f;

    float2 ra[8], rb[8];

    auto load_chunk = [&](int k0) {
        const int kw = k_end - k0;
        #pragma unroll
        for (int it = 0; it < 8; ++it) {
            int s = tid + it * 128;
            int m = s >> 4, kp = s & 15;
            float2 v = make_float2(0.f, 0.f);
            if (m0 + m < M && 2 * kp < kw)
                v = *reinterpret_cast<const float2*>(&A[(size_t)(m0 + m) * lda + k0 + 2 * kp]);
            ra[it] = v;
        }
        #pragma unroll
        for (int it = 0; it < 8; ++it) {
            int s = tid + it * 128;
            int kp = s >> 6, n = s & 63;
            float2 v = make_float2(0.f, 0.f);
            if (n0 + n < N && 2 * kp < kw) {
                const float* p = &B[(size_t)(k0 + 2 * kp) * ldb + n0 + n];
                v.x = __ldg(p);
                v.y = __ldg(p + ldb);
            }
            rb[it] = v;
        }
    };

    auto scatter = [&](int buf) {
        uint32_t* wAH = (uint32_t*)AsPH[buf];
        uint32_t* wAL = (uint32_t*)AsPL[buf];
        uint32_t* wBH = (uint32_t*)BsPH[buf];
        uint32_t* wBL = (uint32_t*)BsPL[buf];
        #pragma unroll
        for (int it = 0; it < 8; ++it) {
            int s = tid + it * 128;
            int m = s >> 4, kp = s & 15;
            uint32_t hi, lo; bf16x2_split(ra[it].x, ra[it].y, hi, lo);
            int word = ((((m >> 5) * 2 + ((m >> 4) & 1)) * 2 + (kp >> 3)) * 32
                        + (m & 7) * 4 + (kp & 3)) * 4
                       + ((m >> 3) & 1) + 2 * ((kp >> 2) & 1);
            wAH[word] = hi; wAL[word] = lo;
        }
        #pragma unroll
        for (int it = 0; it < 8; ++it) {
            int s = tid + it * 128;
            int kp = s >> 6, n = s & 63;
            uint32_t hi, lo; bf16x2_split(rb[it].x, rb[it].y, hi, lo);
            int word = ((((n >> 5) * 2 + (kp >> 3)) * 2 + ((n >> 4) & 1)) * 32
                        + (n & 7) * 4 + (kp & 3)) * 4
                       + ((n >> 3) & 1) * 2 + ((kp >> 2) & 1);
            wBH[word] = hi; wBL[word] = lo;
        }
    };

    // prologue: stage first chunk
    load_chunk(k_beg);
    scatter(0);
    __syncthreads();

    int cur = 0;
    for (int k0 = k_beg; k0 < k_end; k0 += 32) {
        const bool has_next = (k0 + 32 < k_end);
        if (has_next) load_chunk(k0 + 32);   // LDG latency covered by compute below

        // ---- compute chunk k0 from buf[cur] ----
        #pragma unroll
        for (int ks = 0; ks < 2; ks++) {
            uint4 aH[2], aL[2];
            #pragma unroll
            for (int i = 0; i < 2; i++) {
                int base = ((warp_m * 2 + i) * 2 + ks) * 32 + lane;
                aH[i] = AsPH[cur][base];
                aL[i] = AsPL[cur][base];
            }
            uint4 bH[2], bL[2];
            #pragma unroll
            for (int p = 0; p < 2; p++) {
                int base = ((warp_n * 2 + ks) * 2 + p) * 32 + lane;
                bH[p] = BsPH[cur][base];
                bL[p] = BsPL[cur][base];
            }
            #pragma unroll
            for (int i = 0; i < 2; i++) {
                #pragma unroll
                for (int j = 0; j < 4; j++) {
                    int p = j >> 1;
                    uint32_t b0H = (j & 1) ? ((p ? bH[1].z : bH[0].z)) : ((p ? bH[1].x : bH[0].x));
                    uint32_t b1H = (j & 1) ? ((p ? bH[1].w : bH[0].w)) : ((p ? bH[1].y : bH[0].y));
                    uint32_t b0L = (j & 1) ? ((p ? bL[1].z : bL[0].z)) : ((p ? bL[1].x : bL[0].x));
                    uint32_t b1L = (j & 1) ? ((p ? bL[1].w : bL[0].w)) : ((p ? bL[1].y : bL[0].y));
                    mma_bf16(acc[i][j], aH[i].x, aH[i].y, aH[i].z, aH[i].w, b0L, b1L);
                    mma_bf16(acc[i][j], aL[i].x, aL[i].y, aL[i].z, aL[i].w, b0H, b1H);
                    mma_bf16(acc[i][j], aH[i].x, aH[i].y, aH[i].z, aH[i].w, b0H, b1H);
                }
            }
        }

        // ---- scatter chunk k0+32 into the other buffer (overlaps HMMA gaps) ----
        if (has_next) scatter(cur ^ 1);
        __syncthreads();
        cur ^= 1;
    }

    // epilogue
    #pragma unroll
    for (int i = 0; i < 2; i++) {
        #pragma unroll
        for (int j = 0; j < 4; j++) {
            int row = m0 + warp_m * 32 + i * 16 + group;
            int col = n0 + warp_n * 32 + j * 8 + tig * 2;
            #pragma unroll
            for (int q = 0; q < 4; q++) {
                int r = row + (q >> 1) * 8;
                int c = col + (q & 1);
                if (r >= M || c >= N) continue;
                float v = acc[i][j][q];
                if (BIAS) v += bias[c];
                if (ACT == 1) v = fmaxf(v, 0.f);
                if (ACT == 2) v = (v > 20.f) ? v : log1pf(__expf(v));
                size_t idx = (size_t)r * ldc + c;
                if (ATOMIC) atomicAdd(&C[idx], v);
                else        C[idx] = v;
            }
        }
    }
}

// ---------------- fp32 fallback GEMM (input MLP, runs once) ----------------
#define BM 64
#define BN 64
#define BKt 16

template<int ACT, bool BIAS>
__global__ void gemm_k(const float* __restrict__ A, int lda,
                       const float* __restrict__ B, int ldb,
                       const float* __restrict__ bias,
                       float* __restrict__ C, int ldc,
                       int M, int N, int K)
{
    __shared__ float As[BKt][BM];
    __shared__ float Bs[BKt][BN];
    const int tid = threadIdx.x;
    const int tx = tid & 15, ty = tid >> 4;
    const int m0 = blockIdx.y * BM, n0 = blockIdx.x * BN;

    float acc[4][4] = {};
    const int la_m = tid >> 2;
    const int la_k = (tid & 3) * 4;
    const int lb_k = tid >> 4;
    const int lb_n = (tid & 15) * 4;

    for (int k0 = 0; k0 < K; k0 += BKt) {
        #pragma unroll
        for (int j = 0; j < 4; j++) {
            int m = m0 + la_m, k = k0 + la_k + j;
            As[la_k + j][la_m] = (m < M && k < K) ? A[(size_t)m * lda + k] : 0.f;
        }
        #pragma unroll
        for (int j = 0; j < 4; j++) {
            int k = k0 + lb_k, n = n0 + lb_n + j;
            Bs[lb_k][lb_n + j] = (k < K && n < N) ? B[(size_t)k * ldb + n] : 0.f;
        }
        __syncthreads();
        #pragma unroll
        for (int kk = 0; kk < BKt; kk++) {
            float4 ra = *reinterpret_cast<const float4*>(&As[kk][ty * 4]);
            float4 rb = *reinterpret_cast<const float4*>(&Bs[kk][tx * 4]);
            float a4[4] = {ra.x, ra.y, ra.z, ra.w};
            float b4[4] = {rb.x, rb.y, rb.z, rb.w};
            #pragma unroll
            for (int i = 0; i < 4; i++)
                #pragma unroll
                for (int j = 0; j < 4; j++)
                    acc[i][j] = fmaf(a4[i], b4[j], acc[i][j]);
        }
        __syncthreads();
    }

    #pragma unroll
    for (int i = 0; i < 4; i++) {
        int m = m0 + ty * 4 + i;
        if (m >= M) continue;
        #pragma unroll
        for (int j = 0; j < 4; j++) {
            int n = n0 + tx * 4 + j;
            if (n >= N) continue;
            float v = acc[i][j];
            if (BIAS) v += bias[n];
            if (ACT == 1) v = fmaxf(v, 0.f);
            C[(size_t)m * ldc + n] = v;
        }
    }
}

// ---------------- RMSNorm ----------------
__global__ void rmsnorm_k(const float* __restrict__ x, const float* __restrict__ w,
                          float* __restrict__ out, int D)
{
    int row = blockIdx.x;
    const float* xr = x + (size_t)row * D;
    float ss = 0.f;
    for (int d = threadIdx.x; d < D; d += blockDim.x) { float v = xr[d]; ss += v * v; }
    __shared__ float sm[32];
    for (int o = 16; o; o >>= 1) ss += __shfl_down_sync(0xffffffffu, ss, o);
    if ((threadIdx.x & 31) == 0) sm[threadIdx.x >> 5] = ss;
    __syncthreads();
    if (threadIdx.x < 32) {
        float v = (threadIdx.x < ((blockDim.x + 31) >> 5)) ? sm[threadIdx.x] : 0.f;
        for (int o = 16; o; o >>= 1) v += __shfl_down_sync(0xffffffffu, v, o);
        if (threadIdx.x == 0) sm[0] = v;
    }
    __syncthreads();
    float scale = rsqrtf(sm[0] / (float)D + 1e-5f);
    float* orow = out + (size_t)row * D;
    for (int d = threadIdx.x; d < D; d += blockDim.x) orow[d] = xr[d] * scale * w[d];
}

// ---------------- causal depthwise conv (K=4) + SiLU ----------------
__global__ void conv_silu_k(const float* __restrict__ proj,
                            const float* __restrict__ cw,
                            const float* __restrict__ cb,
                            float* __restrict__ ut)
{
    int gid = blockIdx.x * blockDim.x + threadIdx.x;
    if (gid >= Msz * Isz) return;
    int i = gid % Isz;
    int row = gid / Isz;
    int t = row % Lsz;
    float w0 = cw[i * 4 + 0], w1 = cw[i * 4 + 1], w2 = cw[i * 4 + 2], w3 = cw[i * 4 + 3];
    float acc = cb[i];
    const float* base = proj + (size_t)row * PROJ2 + i;
    if (t >= 3) acc = fmaf(w0, base[-3 * PROJ2], acc);
    if (t >= 2) acc = fmaf(w1, base[-2 * PROJ2], acc);
    if (t >= 1) acc = fmaf(w2, base[-1 * PROJ2], acc);
    acc = fmaf(w3, base[0], acc);
    ut[gid] = acc / (1.f + __expf(-acc));
}

// ---------------- selective-scan + fused dt_proj + D skip + gate ----------------
__global__ void __launch_bounds__(128)
scan_k(const float* __restrict__ ssm,
       const float* __restrict__ ut,
       const float* __restrict__ proj,
       const float* __restrict__ A_log,
       const float* __restrict__ Dp,
       const float* __restrict__ dpw,   // [48, Isz]
       const float* __restrict__ dpb,   // [Isz]
       float* __restrict__ y)
{
    int b = blockIdx.y;
    int ci = blockIdx.x * blockDim.x + threadIdx.x;
    __shared__ float sDt[Lsz][Rlr];
    __shared__ float sB[Lsz][Nst], sC[Lsz][Nst];
    for (int q = threadIdx.x; q < Lsz * 80; q += blockDim.x) {
        int t = q / 80, c = q % 80;
        float v = ssm[(size_t)(b * Lsz + t) * 80 + c];
        if (c < Rlr)            sDt[t][c] = v;
        else if (c < Rlr + Nst) sB[t][c - Rlr] = v;
        else                    sC[t][c - Rlr - Nst] = v;
    }
    __syncthreads();

    float wr[Rlr];
    #pragma unroll
    for (int r = 0; r < Rlr; r++) wr[r] = dpw[(size_t)r * Isz + ci];
    float dbias = dpb[ci];

    float a[Nst];
    #pragma unroll
    for (int n = 0; n < Nst; n++) a[n] = -__expf(A_log[(size_t)ci * Nst + n]);
    float Dv = Dp[ci];
    float s[Nst];
    #pragma unroll
    for (int n = 0; n < Nst; n++) s[n] = 0.f;

    for (int t = 0; t < Lsz; t++) {
        size_t row = (size_t)b * Lsz + t;
        float draw = dbias;
        #pragma unroll
        for (int r = 0; r < Rlr; r++) draw = fmaf(sDt[t][r], wr[r], draw);
        float dtv = (draw > 20.f) ? draw : log1pf(__expf(draw));

        float uv = ut[row * Isz + ci];
        float du = dtv * uv;
        float acc = 0.f;
        #pragma unroll
        for (int n = 0; n < Nst; n++) {
            float dA = __expf(dtv * a[n]);
            s[n] = fmaf(dA, s[n], du * sB[t][n]);
            acc = fmaf(s[n], sC[t][n], acc);
        }
        float g = proj[row * PROJ2 + Isz + ci];
        float sig = 1.f / (1.f + __expf(-g));
        y[row * Isz + ci] = (acc + uv * Dv) * (g * sig);
    }
}

// ---------------- reduction GEMM for tiny-M output head ----------------
__global__ void rk_gemm_k(const float* __restrict__ A, int lda,
                          const float* __restrict__ B, int ldb,
                          const float* __restrict__ bias,
                          float* __restrict__ C, int N, int K, int relu)
{
    int lane = threadIdx.x & 31;
    int kg = threadIdx.x >> 5;
    int n = blockIdx.x * 32 + lane;
    int m = blockIdx.y;
    float acc = 0.f;
    if (n < N) {
        const float* arow = A + (size_t)m * lda;
        for (int k = kg; k < K; k += 8)
            acc = fmaf(arow[k], B[(size_t)k * ldb + n], acc);
    }
    __shared__ float sm[256];
    sm[threadIdx.x] = acc;
    __syncthreads();
    if (kg == 0 && n < N) {
        float v = acc;
        #pragma unroll
        for (int g2 = 1; g2 < 8; g2++) v += sm[g2 * 32 + lane];
        v += bias[n];
        if (relu) v = fmaxf(v, 0.f);
        C[(size_t)m * N + n] = v;
    }
}

// ---------------- final dot ----------------
__global__ void out3_k(const float* __restrict__ o2, const float* __restrict__ w,
                       const float* __restrict__ bb, float* __restrict__ out)
{
    int m = blockIdx.x;
    int tid = threadIdx.x;
    float v = o2[m * 256 + tid] * w[tid];
    for (int o = 16; o; o >>= 1) v += __shfl_down_sync(0xffffffffu, v, o);
    __shared__ float sm[8];
    if ((tid & 31) == 0) sm[tid >> 5] = v;
    __syncthreads();
    if (tid == 0) {
        float t = 0.f;
        #pragma unroll
        for (int g = 0; g < 8; g++) t += sm[g];
        out[m] = t + bb[0];
    }
}

// ---------------- host orchestration ----------------
extern "C" void kernel_launch(void* const* d_in, const int* in_sizes, int n_in,
                              void* d_out, int out_size)
{
    const float* x       = (const float*)d_in[0];
    const float* w_in1   = (const float*)d_in[1];
    const float* b_in1   = (const float*)d_in[2];
    const float* w_in2   = (const float*)d_in[3];
    const float* b_in2   = (const float*)d_in[4];
    const float* w_in3   = (const float*)d_in[5];
    const float* b_in3   = (const float*)d_in[6];
    const float* norm_w  = (const float*)d_in[7];
    const float* ipw     = (const float*)d_in[8];
    const float* cw      = (const float*)d_in[9];
    const float* cb      = (const float*)d_in[10];
    const float* xpw     = (const float*)d_in[11];
    const float* dpw     = (const float*)d_in[12];
    const float* dpb     = (const float*)d_in[13];
    const float* alog    = (const float*)d_in[14];
    const float* dprm    = (const float*)d_in[15];
    const float* opw     = (const float*)d_in[16];
    const float* norm_fw = (const float*)d_in[17];
    const float* w_o1    = (const float*)d_in[18];
    const float* b_o1    = (const float*)d_in[19];
    const float* w_o2    = (const float*)d_in[20];
    const float* b_o2    = (const float*)d_in[21];
    const float* w_o3    = (const float*)d_in[22];
    const float* b_o3    = (const float*)d_in[23];

    float *h, *hn, *proj, *ut, *ssmb, *yb, *f1, *f2, *o1b, *o2b;
    cudaGetSymbolAddress((void**)&h,    g_h);
    cudaGetSymbolAddress((void**)&hn,   g_hn);
    cudaGetSymbolAddress((void**)&proj, g_proj);
    cudaGetSymbolAddress((void**)&ut,   g_ut);
    cudaGetSymbolAddress((void**)&ssmb, g_ssm);
    cudaGetSymbolAddress((void**)&yb,   g_y);
    cudaGetSymbolAddress((void**)&f1,   g_f1);
    cudaGetSymbolAddress((void**)&f2,   g_f2);
    cudaGetSymbolAddress((void**)&o1b,  g_o1);
    cudaGetSymbolAddress((void**)&o2b,  g_o2);

    dim3 blk256(256), blk128(128);

    // ---- input MLP (fp32, runs once) ----
    gemm_k<1, true><<<dim3(4, 8, 1), blk256>>>(
        x, Fin, w_in1, 256, b_in1, f1, 256, Msz, 256, Fin);
    gemm_k<1, true><<<dim3(4, 8, 1), blk256>>>(
        f1, 256, w_in2, 256, b_in2, f2, 256, Msz, 256, 256);
    gemm_k<0, true><<<dim3(12, 8, 1), blk256>>>(
        f2, 256, w_in3, Dm, b_in3, h, Dm, Msz, Dm, 256);

    // ---- 32 mamba layers ----
    for (int l = 0; l < NL; l++) {
        const float* nw_l  = norm_w + (size_t)l * Dm;
        const float* ipw_l = ipw    + (size_t)l * Dm * PROJ2;
        const float* cw_l  = cw     + (size_t)l * Isz * Kcv;
        const float* cb_l  = cb     + (size_t)l * Isz;
        const float* xpw_l = xpw    + (size_t)l * Isz * 80;
        const float* dpw_l = dpw    + (size_t)l * Rlr * Isz;
        const float* dpb_l = dpb    + (size_t)l * Isz;
        const float* al_l  = alog   + (size_t)l * Isz * Nst;
        const float* dp_l  = dprm   + (size_t)l * Isz;
        const float* opw_l = opw    + (size_t)l * Isz * Dm;

        rmsnorm_k<<<Msz, blk256>>>(h, nw_l, hn, Dm);

        // in_proj: [480,768] x [768,3072], split-K=2 + atomics (zeroed first)
        cudaMemsetAsync(proj, 0, (size_t)Msz * PROJ2 * sizeof(float));
        mma_gemm_k<0, false, true><<<dim3(48, 8, 2), blk128>>>(
            hn, Dm, ipw_l, PROJ2, nullptr, proj, PROJ2, Msz, PROJ2, Dm);

        conv_silu_k<<<(Msz * Isz + 255) / 256, blk256>>>(proj, cw_l, cb_l, ut);

        // x_proj: [480,1536] x [1536,80], split-K=8 with atomics
        cudaMemsetAsync(ssmb, 0, (size_t)Msz * 80 * sizeof(float));
        mma_gemm_k<0, false, true><<<dim3(2, 8, 8), blk128>>>(
            ut, Isz, xpw_l, 80, nullptr, ssmb, 80, Msz, 80, Isz);

        // scan with fused dt_proj (exact fp32 dt)
        scan_k<<<dim3(Isz / 128, Bsz), blk128>>>(
            ssmb, ut, proj, al_l, dp_l, dpw_l, dpb_l, yb);

        // out_proj: [480,1536] x [1536,768], split-K=2, atomic residual add into h
        mma_gemm_k<0, false, true><<<dim3(12, 8, 2), blk128>>>(
            yb, Isz, opw_l, Dm, nullptr, h, Dm, Msz, Dm, Isz);
    }

    // ---- final norm + output head ----
    rmsnorm_k<<<Msz, blk256>>>(h, norm_fw, hn, Dm);
    rk_gemm_k<<<dim3(8, Bsz), blk256>>>(hn, Dm * Lsz, w_o1, 256, b_o1, o1b, 256, Dm * Lsz, 1);
    rk_gemm_k<<<dim3(8, Bsz), blk256>>>(o1b, 256, w_o2, 256, b_o2, o2b, 256, 256, 1);
    out3_k<<<Bsz, blk256>>>(o2b, w_o3, b_o3, (float*)d_out);
}